// round 10
// baseline (speedup 1.0000x reference)
#include <cuda_runtime.h>
#include <cstdint>

// Grapher, two launches:
//  K1 (grid 128 x 1024): scan + segment means + GEMM1 (mean@W1) + pair build
//     -> X fp32 [b][p][152] in global scratch (cols 150,151 zeroed).
//  K2 (grid 256 = batch x row-half, 608 thr, 2 blocks/SM): 2-layer MLP GEMM,
//     weights streamed in 19-row k-chunks via a 2-slot cp.async ring
//     (chunks 0-7 = Wm, 8-15 = W2), X in smem [32][153], y in registers.
//  R9 fix: final chunk drains with wait_group 0.
//  R10 fix: __syncthreads() after the prologue — bias/pad STS must be visible
//  before the unsynchronized accumulator-init reads (this was the rel_err~8).

#define B_   128
#define S_   1024
#define H_   768
#define C_   150
#define NN   8
#define SEPID 3

typedef unsigned long long u64;

// ---------------- global scratch ----------------
__device__ __align__(16) float g_X[B_ * 64 * 152];     // 4.98 MB

// ---------------- helpers ----------------
__device__ __forceinline__ uint32_t sptr(const void* p) {
    return (uint32_t)__cvta_generic_to_shared(p);
}
__device__ __forceinline__ void cp8(uint32_t s, const void* g) {
    asm volatile("cp.async.ca.shared.global [%0], [%1], 8;" :: "r"(s), "l"(g));
}
__device__ __forceinline__ void cp4(uint32_t s, const void* g) {
    asm volatile("cp.async.ca.shared.global [%0], [%1], 4;" :: "r"(s), "l"(g));
}
#define CP_COMMIT() asm volatile("cp.async.commit_group;" ::: "memory")
#define CP_WAIT1()  asm volatile("cp.async.wait_group 1;" ::: "memory")
#define CP_WAIT0()  asm volatile("cp.async.wait_group 0;" ::: "memory")

__device__ __forceinline__ void ffma2(u64& d, u64 a, u64 b) {
    asm("fma.rn.f32x2 %0, %1, %2, %0;" : "+l"(d) : "l"(a), "l"(b));
}
__device__ __forceinline__ u64 add2(u64 a, u64 b) {
    u64 r; asm("add.rn.f32x2 %0, %1, %2;" : "=l"(r) : "l"(a), "l"(b)); return r;
}
__device__ __forceinline__ u64 dup2(float x) {
    u64 r; asm("mov.b64 %0, {%1, %1};" : "=l"(r) : "f"(x)); return r;
}
__device__ __forceinline__ void unpack2(u64 v, float& lo, float& hi) {
    asm("mov.b64 {%0, %1}, %2;" : "=f"(lo), "=f"(hi) : "l"(v));
}
__device__ __forceinline__ u64 lds64(uint32_t a) {
    u64 v; asm volatile("ld.shared.u64 %0, [%1];" : "=l"(v) : "r"(a)); return v;
}
__device__ __forceinline__ float lds32(uint32_t a) {
    float v; asm volatile("ld.shared.f32 %0, [%1];" : "=f"(v) : "r"(a)); return v;
}
__device__ __forceinline__ void lds_v2(uint32_t a, u64& x, u64& y) {
    asm volatile("ld.shared.v2.u64 {%0, %1}, [%2];" : "=l"(x), "=l"(y) : "r"(a));
}
__device__ __forceinline__ void sts64(uint32_t a, u64 v) {
    asm volatile("st.shared.u64 [%0], %1;" :: "r"(a), "l"(v) : "memory");
}
__device__ __forceinline__ void sts32(uint32_t a, float v) {
    asm volatile("st.shared.f32 [%0], %1;" :: "r"(a), "f"(v) : "memory");
}

// =======================================================================
// K1 : scan + means + GEMM1 + pair build -> g_X
// =======================================================================
#define NT1 1024
// smem float offsets
#define OFF_P   0                 // means partials P[5][8][772] = 30880; then GEMM1 partials
#define OFF_MT  30880             // meansT[768][8] = 6144
#define OFF_G   37024             // 8*152
#define OFF_B1  38240             // 152
#define OFF_BND 38392             // 16 ints
#define SM1_FLOATS 38408
#define SM1_BYTES (SM1_FLOATS * 4)   // 153632

__global__ __launch_bounds__(NT1, 1)
void grapher_k1(const int* __restrict__ ids,
                const float* __restrict__ feat,
                const float* __restrict__ W1, const float* __restrict__ b1)
{
    extern __shared__ float sm[];
    float* sP  = sm + OFF_P;
    float* sMT = sm + OFF_MT;
    float* sG  = sm + OFF_G;
    float* sB1 = sm + OFF_B1;
    int*   sBnd = (int*)(sm + OFF_BND);

    const int tid = threadIdx.x;
    const int b   = blockIdx.x;
    const uint32_t mt_b = sptr(sMT);
    const uint32_t pp_b = sptr(sP);

    // ---- scan (warp 0) + b1 load ----
    if (tid < 32) {
        const int lane = tid;
        if (lane < 16) sBnd[lane] = S_;
        __syncwarp();
        const int4* rp = (const int4*)(ids + (size_t)b * S_) + lane * 8;
        int4 v[8];
        int cnt = 0;
#pragma unroll
        for (int q = 0; q < 8; q++) {
            v[q] = rp[q];
            cnt += (v[q].x == SEPID) + (v[q].y == SEPID) +
                   (v[q].z == SEPID) + (v[q].w == SEPID);
        }
        int pre = cnt;
#pragma unroll
        for (int off = 1; off < 32; off <<= 1) {
            int t = __shfl_up_sync(0xffffffffu, pre, off);
            if (lane >= off) pre += t;
        }
        int run = pre - cnt;
#pragma unroll
        for (int q = 0; q < 8; q++) {
            int base = lane * 32 + q * 4;
            if (v[q].x == SEPID) { run++; if (run <= NN) sBnd[run] = base + 0; }
            if (v[q].y == SEPID) { run++; if (run <= NN) sBnd[run] = base + 1; }
            if (v[q].z == SEPID) { run++; if (run <= NN) sBnd[run] = base + 2; }
            if (v[q].w == SEPID) { run++; if (run <= NN) sBnd[run] = base + 3; }
        }
    } else if (tid >= 64 && tid < 64 + 152) {
        int i = tid - 64;
        sB1[i] = (i < C_) ? b1[i] : 0.f;
    }
    __syncthreads();

    // ---- means partials: 5 contiguous token tiles x 192 float4 cols ----
    if (tid < 960) {
        const int tg  = tid / 192;
        const int col = tid - tg * 192;
        const int T   = sBnd[NN];
        const int tb0 = (T * tg) / 5;
        const int tb1 = (T * (tg + 1)) / 5;
        const float4* f4 = (const float4*)(feat + (size_t)b * S_ * H_) + col;
        float* P = sP + tg * 6176 + col * 4;
#pragma unroll 1
        for (int n = 0; n < NN; n++) {
            int lo = (n == 0) ? 0 : sBnd[n] + 1;
            int hi = sBnd[n + 1];
            if (lo < tb0) lo = tb0;
            if (hi > tb1) hi = tb1;
            float4 a0 = make_float4(0.f, 0.f, 0.f, 0.f), a1 = a0, a2 = a0, a3 = a0;
            int t = lo;
            for (; t + 3 < hi; t += 4) {
                float4 v0 = f4[(t + 0) * 192];
                float4 v1 = f4[(t + 1) * 192];
                float4 v2 = f4[(t + 2) * 192];
                float4 v3 = f4[(t + 3) * 192];
                a0.x += v0.x; a0.y += v0.y; a0.z += v0.z; a0.w += v0.w;
                a1.x += v1.x; a1.y += v1.y; a1.z += v1.z; a1.w += v1.w;
                a2.x += v2.x; a2.y += v2.y; a2.z += v2.z; a2.w += v2.w;
                a3.x += v3.x; a3.y += v3.y; a3.z += v3.z; a3.w += v3.w;
            }
            for (; t < hi; t++) {
                float4 v = f4[t * 192];
                a0.x += v.x; a0.y += v.y; a0.z += v.z; a0.w += v.w;
            }
            float4 s;
            s.x = (a0.x + a1.x) + (a2.x + a3.x);
            s.y = (a0.y + a1.y) + (a2.y + a3.y);
            s.z = (a0.z + a1.z) + (a2.z + a3.z);
            s.w = (a0.w + a1.w) + (a2.w + a3.w);
            *(float4*)(P + n * 772) = s;
        }
    } else {
        // 2 spare warps: L2-prefetch W1 for GEMM1
        const float4* w4 = (const float4*)W1;
        for (int i = tid - 960; i < (H_ * C_) / 4; i += 64)
            asm volatile("prefetch.global.L2 [%0];" :: "l"(w4 + i));
    }
    __syncthreads();

    // ---- combine tiles + 1/len -> meansT[k][8] ----
    if (tid < H_) {
        float inv[8];
#pragma unroll
        for (int n = 0; n < NN; n++) {
            int lo = (n == 0) ? 0 : sBnd[n] + 1;
            int len = sBnd[n + 1] - lo;
            if (len < 1) len = 1;
            inv[n] = 1.0f / (float)len;
        }
        const float* P = sP + tid;
#pragma unroll
        for (int n = 0; n < NN; n++) {
            float s = ((P[n * 772] + P[6176 + n * 772]) +
                       (P[12352 + n * 772] + P[18528 + n * 772])) + P[24704 + n * 772];
            sMT[tid * 8 + n] = s * inv[n];
        }
    }
    __syncthreads();                      // P region free for GEMM1 partials

    // ---- GEMM1: g[n][c] = sum_k meansT[k][n] * W1[k][c] ----
    u64 g_acc[2][4];
    int ks = 0, cpair = 0;
    if (tid < 600) {
        ks = tid / 75; cpair = tid - ks * 75;
#pragma unroll
        for (int cc = 0; cc < 2; cc++)
#pragma unroll
            for (int q = 0; q < 4; q++) g_acc[cc][q] = 0ull;
        const float2* wrow = (const float2*)(W1 + (size_t)(ks * 96) * C_) + cpair;
#pragma unroll 4
        for (int kk = 0; kk < 96; kk++) {
            int k = ks * 96 + kk;
            float2 w = __ldg(wrow + kk * 75);
            u64 dw0 = dup2(w.x), dw1 = dup2(w.y);
            u64 m01, m23, m45, m67;
            uint32_t ma = mt_b + (uint32_t)(k * 8) * 4u;
            lds_v2(ma, m01, m23);
            lds_v2(ma + 16u, m45, m67);
            ffma2(g_acc[0][0], m01, dw0); ffma2(g_acc[0][1], m23, dw0);
            ffma2(g_acc[0][2], m45, dw0); ffma2(g_acc[0][3], m67, dw0);
            ffma2(g_acc[1][0], m01, dw1); ffma2(g_acc[1][1], m23, dw1);
            ffma2(g_acc[1][2], m45, dw1); ffma2(g_acc[1][3], m67, dw1);
        }
    }
    __syncthreads();
    if (tid < 600) {                      // partials [ks][e][150]
#pragma unroll
        for (int cc = 0; cc < 2; cc++)
#pragma unroll
            for (int q = 0; q < 4; q++)
                sts64(pp_b + (uint32_t)(ks * 1200 + (cc * 4 + q) * 150 + 2 * cpair) * 4u,
                      g_acc[cc][q]);
    }
    __syncthreads();
    if (tid < 600) {                      // reduce 8 slices -> sG
        u64 s = lds64(pp_b + (uint32_t)(2 * tid) * 4u);
#pragma unroll
        for (int k8 = 1; k8 < 8; k8++)
            s = add2(s, lds64(pp_b + (uint32_t)(k8 * 1200 + 2 * tid) * 4u));
        int e = tid / 75, cp2 = tid - e * 75;
        int cc = e >> 2, q = e & 3, c = 2 * cp2 + cc;
        float lo, hi; unpack2(s, lo, hi);
        sG[(2 * q + 0) * 152 + c] = lo;
        sG[(2 * q + 1) * 152 + c] = hi;
    }
    __syncthreads();

    // ---- pair build -> g_X[b][p][152] (cols 150,151 zero) ----
    {
        const int p  = tid >> 4;          // 0..63
        const int cs = tid & 15;          // 16 col segments of 10
        const int i  = p >> 3, j = p & 7;
        const int c0 = cs * 10;
        float* dst = g_X + ((size_t)b * 64 + p) * 152;
#pragma unroll
        for (int m = 0; m < 10; m++) {
            int c = c0 + m;
            if (c < 152) {
                float v = 0.f;
                if (c < C_)
                    v = fmaxf(sG[i * 152 + c] - sG[j * 152 + c] + sB1[c], 0.f);
                dst[c] = v;
            }
        }
    }
}

// =======================================================================
// K2 : per (batch, row-half) 2-layer GEMM with chunked weight ring
// =======================================================================
#define NT2 608
#define CHK 19
#define WSLOT (CHK * 152)        // 2888 floats
#define K2_W  0                  // 2 slots * 2888 = 5776
#define K2_X  5776               // 32*153 = 4896
#define K2_BM 10672              // 152
#define K2_B2 10824              // 152
#define SM2_FLOATS 10976
#define SM2_BYTES (SM2_FLOATS * 4)   // 43904

__global__ __launch_bounds__(NT2, 2)
void grapher_k2(const float* __restrict__ Wm, const float* __restrict__ bm,
                const float* __restrict__ W2, const float* __restrict__ b2,
                float* __restrict__ out)
{
    extern __shared__ float sm[];
    const int tid = threadIdx.x;
    const int b   = blockIdx.x >> 1;
    const int h   = blockIdx.x & 1;
    const int cg  = tid >> 5;            // 0..18 col group of 8
    const int r   = tid & 31;            // row within half
    const int c0  = cg * 8;
    const uint32_t w_b = sptr(sm + K2_W);
    const uint32_t x_b = sptr(sm + K2_X);

    // ---- prologue: X tile (cp4, 8 per thread), biases, pad-zero W cols ----
    {
        const float* src = g_X + ((size_t)b * 64 + h * 32) * 152;
#pragma unroll
        for (int q = 0; q < 8; q++) {
            int i = tid + q * NT2;        // 0..4863
            int row = i / 152, c = i - row * 152;
            cp4(x_b + (uint32_t)(row * 153 + c) * 4u, src + row * 152 + c);
        }
    }
    if (tid < 152) {
        sm[K2_BM + tid] = (tid < C_) ? bm[tid] : 0.f;
        sm[K2_B2 + tid] = (tid < C_) ? b2[tid] : 0.f;
    } else if (tid >= 256 && tid < 256 + 76) {
        int i = tid - 256;
        int slot = i / 38, rr = (i % 38) >> 1, c = 150 + (i & 1);
        sm[K2_W + slot * WSLOT + rr * 152 + c] = 0.f;
    }
    CP_COMMIT();                          // group: X tile

    // weight chunk issuer: chunk c in 0..15 (0-7 = Wm, 8-15 = W2)
    auto issue_chunk = [&](int c) {
        const float* W = (c < 8) ? Wm : W2;
        const int k0 = (c & 7) * CHK;
        const uint32_t dst0 = w_b + (uint32_t)((c & 1) * WSLOT) * 4u;
#pragma unroll
        for (int q = 0; q < 3; q++) {
            int m = tid + q * NT2;        // 0..1424 (19*75)
            if (m < CHK * 75) {
                int kk = m / 75, cl = m - kk * 75;
                int k = k0 + kk;
                uint32_t d = dst0 + (uint32_t)(kk * 152 + 2 * cl) * 4u;
                if (k < C_) cp8(d, W + k * C_ + 2 * cl);
                else        sts64(d, 0ull);
            }
        }
        CP_COMMIT();
    };

    issue_chunk(0);
    issue_chunk(1);

    // R10 FIX: bias/pad plain-STS must be visible to ALL threads before the
    // unsynchronized acc-init reads below. (This race was the rel_err~8.)
    __syncthreads();

    u64 acc[4];
#pragma unroll
    for (int L = 0; L < 2; L++) {
        const uint32_t bias_b = sptr(sm + (L == 0 ? K2_BM : K2_B2));
#pragma unroll
        for (int cp = 0; cp < 4; cp++)
            acc[cp] = lds64(bias_b + (uint32_t)(c0 + 2 * cp) * 4u);

#pragma unroll 1
        for (int c8 = 0; c8 < 8; c8++) {
            const int c = L * 8 + c8;
            // final chunk has no successor commit -> drain fully (R9 fix)
            if (c == 15) { CP_WAIT0(); } else { CP_WAIT1(); }
            __syncthreads();              // chunk c (and X on c=0) visible to all
            {
                const uint32_t wbase = w_b + (uint32_t)((c & 1) * WSLOT + c0) * 4u;
                const uint32_t xbase = x_b + (uint32_t)(r * 153 + (c & 7) * CHK) * 4u;
#pragma unroll
                for (int kk = 0; kk < CHK; kk++) {
                    float xv = lds32(xbase + (uint32_t)kk * 4u);
                    u64 d = dup2(xv);
                    u64 w0, w1, w2, w3;
                    uint32_t wa = wbase + (uint32_t)(kk * 152) * 4u;
                    lds_v2(wa, w0, w1);
                    lds_v2(wa + 16u, w2, w3);
                    ffma2(acc[0], d, w0); ffma2(acc[1], d, w1);
                    ffma2(acc[2], d, w2); ffma2(acc[3], d, w3);
                }
            }
            __syncthreads();              // all warps done with slot before refill
            if (c + 2 < 16) issue_chunk(c + 2);
        }

        if (L == 0) {
            // y = relu(acc) -> X region (becomes layer-2 input)
#pragma unroll
            for (int cp = 0; cp < 4; cp++) {
                float lo, hi; unpack2(acc[cp], lo, hi);
                sts32(x_b + (uint32_t)(r * 153 + c0 + 2 * cp) * 4u, fmaxf(lo, 0.f));
                sts32(x_b + (uint32_t)(r * 153 + c0 + 2 * cp + 1) * 4u, fmaxf(hi, 0.f));
            }
            __syncthreads();
        }
    }

    // ---- epilogue: out[p][b][c] = acc ----
    {
        const int p = h * 32 + r;
        float* o = out + ((size_t)p * B_ + b) * C_;
#pragma unroll
        for (int cp = 0; cp < 4; cp++) {
            int cc = c0 + 2 * cp;
            if (cc < C_) {
                float lo, hi; unpack2(acc[cp], lo, hi);
                *(float2*)(o + cc) = make_float2(lo, hi);
            }
        }
    }
}

// =======================================================================
extern "C" void kernel_launch(void* const* d_in, const int* in_sizes, int n_in,
                              void* d_out, int out_size)
{
    const int*   ids  = (const int*)d_in[0];
    const float* feat = (const float*)d_in[1];
    const float* W1 = (const float*)d_in[2];
    const float* b1 = (const float*)d_in[3];
    const float* Wm = (const float*)d_in[4];
    const float* bm = (const float*)d_in[5];
    const float* W2 = (const float*)d_in[6];
    const float* b2 = (const float*)d_in[7];
    float* out = (float*)d_out;

    cudaFuncSetAttribute(grapher_k1, cudaFuncAttributeMaxDynamicSharedMemorySize, SM1_BYTES);
    cudaFuncSetAttribute(grapher_k2, cudaFuncAttributeMaxDynamicSharedMemorySize, SM2_BYTES);

    grapher_k1<<<B_, NT1, SM1_BYTES>>>(ids, feat, W1, b1);
    grapher_k2<<<B_ * 2, NT2, SM2_BYTES>>>(Wm, bm, W2, b2, out);
}

// round 11
// speedup vs baseline: 1.4491x; 1.4491x over previous
#include <cuda_runtime.h>
#include <cuda_bf16.h>
#include <cstdint>

// Grapher fused kernel, round 11: pair-GEMMs on tensor cores via mma.sync bf16
// (m16n8k8, 3-term hi/lo split for fp32-grade accuracy), everything else the
// proven fp32 path. One block per batch, 608 threads.
//
//  scan -> [means (384 thr) || Wm/W2 -> bf16 hi/lo transpose (224 thr)]
//       -> GEMM1 fp32 FFMA2 (mean@W1) -> sG
//       -> pair build relu(g_i-g_j+b1) -> Xhi/Xlo bf16 [64][152]
//       -> GEMM2 mma.sync (y=relu(X@Wm+bm), re-split to bf16 in place)
//       -> GEMM3 mma.sync (out = y@W2 + b2)

#define B_   128
#define S_   1024
#define H_   768
#define C_   150
#define NN   8
#define SEPID 3
#define NTHR 608          // 19 warps

// ---- shared memory byte offsets ----
#define O_WMHI 0          // [152][152] bf16 = 46208 B  (W^T: [n][k])
#define O_WMLO 46208
#define O_W2HI 92416
#define O_W2LO 138624
#define O_X    184832     // Xhi bf16 [64][152] = 19456 B ; fp32 scratch earlier
#define O_XLO  204288     // Xlo bf16 [64][152]
#define O_SG   223744     // g fp32 [8][152] = 4864 B
#define O_B1   228608     // 152 f32
#define O_BM   229216
#define O_B2   229824
#define O_BND  230432     // 16 int
#define SMEM_BYTES 230496

typedef unsigned long long u64;

__device__ __forceinline__ uint32_t sptr(const void* p) {
    return (uint32_t)__cvta_generic_to_shared(p);
}
__device__ __forceinline__ void ffma2(u64& d, u64 a, u64 b) {
    asm("fma.rn.f32x2 %0, %1, %2, %0;" : "+l"(d) : "l"(a), "l"(b));
}
__device__ __forceinline__ u64 add2(u64 a, u64 b) {
    u64 r; asm("add.rn.f32x2 %0, %1, %2;" : "=l"(r) : "l"(a), "l"(b)); return r;
}
__device__ __forceinline__ u64 dup2(float x) {
    u64 r; asm("mov.b64 %0, {%1, %1};" : "=l"(r) : "f"(x)); return r;
}
__device__ __forceinline__ void unpack2(u64 v, float& lo, float& hi) {
    asm("mov.b64 {%0, %1}, %2;" : "=f"(lo), "=f"(hi) : "l"(v));
}
__device__ __forceinline__ u64 lds64(uint32_t a) {
    u64 v; asm volatile("ld.shared.u64 %0, [%1];" : "=l"(v) : "r"(a)); return v;
}
__device__ __forceinline__ void lds_v2(uint32_t a, u64& x, u64& y) {
    asm volatile("ld.shared.v2.u64 {%0, %1}, [%2];" : "=l"(x), "=l"(y) : "r"(a));
}
__device__ __forceinline__ void sts64(uint32_t a, u64 v) {
    asm volatile("st.shared.u64 [%0], %1;" :: "r"(a), "l"(v) : "memory");
}
__device__ __forceinline__ uint32_t lds_u32(uint32_t a) {
    uint32_t v; asm volatile("ld.shared.b32 %0, [%1];" : "=r"(v) : "r"(a)); return v;
}
__device__ __forceinline__ void sts_u32(uint32_t a, uint32_t v) {
    asm volatile("st.shared.b32 [%0], %1;" :: "r"(a), "r"(v) : "memory");
}
__device__ __forceinline__ float lds_f32(uint32_t a) {
    float v; asm volatile("ld.shared.f32 %0, [%1];" : "=f"(v) : "r"(a)); return v;
}
__device__ __forceinline__ unsigned short f2bf(float x) {
    __nv_bfloat16 h = __float2bfloat16_rn(x);
    return *reinterpret_cast<unsigned short*>(&h);
}
__device__ __forceinline__ float bf2f(unsigned short u) {
    __nv_bfloat16 h = *reinterpret_cast<__nv_bfloat16*>(&u);
    return __bfloat162float(h);
}
__device__ __forceinline__ uint32_t pack_bf2(float a, float b) {
    return (uint32_t)f2bf(a) | ((uint32_t)f2bf(b) << 16);
}

// D(16x8) += A(16x8 bf16,row) * B(8x8 bf16,col), fp32 accum, warp-collective.
__device__ __forceinline__ void mma8(float c[4], uint32_t a0, uint32_t a1, uint32_t b0) {
    asm volatile(
        "mma.sync.aligned.m16n8k8.row.col.f32.bf16.bf16.f32 "
        "{%0,%1,%2,%3}, {%4,%5}, {%6}, {%0,%1,%2,%3};"
        : "+f"(c[0]), "+f"(c[1]), "+f"(c[2]), "+f"(c[3])
        : "r"(a0), "r"(a1), "r"(b0));
}

__global__ __launch_bounds__(NTHR, 1)
void grapher_kernel(const int* __restrict__ ids,
                    const float* __restrict__ feat,
                    const float* __restrict__ W1, const float* __restrict__ b1,
                    const float* __restrict__ Wm, const float* __restrict__ bm,
                    const float* __restrict__ W2, const float* __restrict__ b2,
                    float* __restrict__ out)
{
    extern __shared__ char smc[];
    const uint32_t sb = sptr(smc);
    float* sG  = (float*)(smc + O_SG);
    float* sB1 = (float*)(smc + O_B1);
    float* sBM = (float*)(smc + O_BM);
    float* sB2 = (float*)(smc + O_B2);
    int*   sBnd = (int*)(smc + O_BND);
    float* sX32 = (float*)(smc + O_X);     // fp32 scratch phase (means/GEMM1)

    const int tid = threadIdx.x;
    const int b   = blockIdx.x;
    const uint32_t x_b = sb + O_X;         // byte base of scratch / Xhi

    // ---------- phase 1: separator scan (warp 0) + bias loads ----------
    if (tid < 32) {
        const int lane = tid;
        if (lane < 16) sBnd[lane] = S_;
        __syncwarp();
        const int4* rp = (const int4*)(ids + (size_t)b * S_) + lane * 8;
        int4 v[8];
        int cnt = 0;
#pragma unroll
        for (int q = 0; q < 8; q++) {
            v[q] = rp[q];
            cnt += (v[q].x == SEPID) + (v[q].y == SEPID) +
                   (v[q].z == SEPID) + (v[q].w == SEPID);
        }
        int pre = cnt;
#pragma unroll
        for (int off = 1; off < 32; off <<= 1) {
            int t = __shfl_up_sync(0xffffffffu, pre, off);
            if (lane >= off) pre += t;
        }
        int run = pre - cnt;
#pragma unroll
        for (int q = 0; q < 8; q++) {
            int base = lane * 32 + q * 4;
            if (v[q].x == SEPID) { run++; if (run <= NN) sBnd[run] = base + 0; }
            if (v[q].y == SEPID) { run++; if (run <= NN) sBnd[run] = base + 1; }
            if (v[q].z == SEPID) { run++; if (run <= NN) sBnd[run] = base + 2; }
            if (v[q].w == SEPID) { run++; if (run <= NN) sBnd[run] = base + 3; }
        }
    } else if (tid >= 448 && tid < 448 + 152) {
        int i = tid - 448;
        sB1[i] = (i < C_) ? b1[i] : 0.f;
        sBM[i] = (i < C_) ? bm[i] : 0.f;
        sB2[i] = (i < C_) ? b2[i] : 0.f;
    }
    __syncthreads();

    // ---------- phase 2: means (tid<384) || weight convert (tid>=384) ----------
    if (tid < 384) {
        // segment means -> meansT[k][8] fp32 in the X scratch region
        const float2* f2 = (const float2*)(feat + (size_t)b * S_ * H_) + tid;
#pragma unroll 1
        for (int n = 0; n < NN; n++) {
            int lo = (n == 0) ? 0 : sBnd[n] + 1;
            int hi = sBnd[n + 1];
            float2 a0 = make_float2(0.f, 0.f), a1 = a0, a2 = a0, a3 = a0;
            int t = lo;
            for (; t + 3 < hi; t += 4) {
                float2 v0 = f2[(t + 0) * 384];
                float2 v1 = f2[(t + 1) * 384];
                float2 v2 = f2[(t + 2) * 384];
                float2 v3 = f2[(t + 3) * 384];
                a0.x += v0.x; a0.y += v0.y;
                a1.x += v1.x; a1.y += v1.y;
                a2.x += v2.x; a2.y += v2.y;
                a3.x += v3.x; a3.y += v3.y;
            }
            for (; t < hi; t++) {
                float2 v = f2[t * 384];
                a0.x += v.x; a0.y += v.y;
            }
            float sx = (a0.x + a1.x) + (a2.x + a3.x);
            float sy = (a0.y + a1.y) + (a2.y + a3.y);
            int c = hi - lo; if (c < 1) c = 1;
            float inv = 1.0f / (float)c;
            sX32[(2 * tid + 0) * 8 + n] = sx * inv;
            sX32[(2 * tid + 1) * 8 + n] = sy * inv;
        }
    } else {
        // Wm/W2 [k][n] fp32 (global) -> [n][k] bf16 hi/lo in smem, pads zeroed
#pragma unroll 1
        for (int layer = 0; layer < 2; layer++) {
            const float* src = layer ? W2 : Wm;
            unsigned short* dh = (unsigned short*)(smc + (layer ? O_W2HI : O_WMHI));
            unsigned short* dl = (unsigned short*)(smc + (layer ? O_W2LO : O_WMLO));
            for (int idx = tid - 384; idx < 152 * 152; idx += 224) {
                int k = idx / 152, n = idx - k * 152;   // consecutive idx -> consecutive n (coalesced)
                float v = (k < C_ && n < C_) ? __ldg(src + k * C_ + n) : 0.f;
                unsigned short h = f2bf(v);
                dh[n * 152 + k] = h;
                dl[n * 152 + k] = f2bf(v - bf2f(h));
            }
        }
    }
    __syncthreads();

    // ---------- GEMM1 (fp32 FFMA2): g[n][c] = sum_k meansT[k][n] * W1[k][c] ----------
    u64 g_acc[2][4];
    int ks1 = 0, cpair = 0;
    if (tid < 600) {
        ks1 = tid / 75; cpair = tid - ks1 * 75;
#pragma unroll
        for (int cc = 0; cc < 2; cc++)
#pragma unroll
            for (int q = 0; q < 4; q++) g_acc[cc][q] = 0ull;
        const float2* wrow = (const float2*)(W1 + (size_t)(ks1 * 96) * C_) + cpair;
#pragma unroll 4
        for (int kk = 0; kk < 96; kk++) {
            int k = ks1 * 96 + kk;
            float2 w = __ldg(wrow + kk * 75);
            u64 dw0 = dup2(w.x), dw1 = dup2(w.y);
            u64 m01, m23, m45, m67;
            uint32_t ma = x_b + (uint32_t)(k * 8) * 4u;
            lds_v2(ma, m01, m23);
            lds_v2(ma + 16u, m45, m67);
            ffma2(g_acc[0][0], m01, dw0); ffma2(g_acc[0][1], m23, dw0);
            ffma2(g_acc[0][2], m45, dw0); ffma2(g_acc[0][3], m67, dw0);
            ffma2(g_acc[1][0], m01, dw1); ffma2(g_acc[1][1], m23, dw1);
            ffma2(g_acc[1][2], m45, dw1); ffma2(g_acc[1][3], m67, dw1);
        }
    }
    __syncthreads();                      // meansT reads done; reuse region
    if (tid < 600) {                      // partials [ks][e][150]
#pragma unroll
        for (int cc = 0; cc < 2; cc++)
#pragma unroll
            for (int q = 0; q < 4; q++)
                sts64(x_b + (uint32_t)(ks1 * 1200 + (cc * 4 + q) * 150 + 2 * cpair) * 4u,
                      g_acc[cc][q]);
    }
    __syncthreads();
    if (tid < 600) {                      // reduce 8 slices -> sG (cols 0..149)
        u64 s = lds64(x_b + (uint32_t)(2 * tid) * 4u);
#pragma unroll
        for (int k8 = 1; k8 < 8; k8++)
            s = add2(s, lds64(x_b + (uint32_t)(k8 * 1200 + 2 * tid) * 4u));
        int e = tid / 75, cp2 = tid - e * 75;
        int cc = e >> 2, q = e & 3, c = 2 * cp2 + cc;
        float lo, hi; unpack2(s, lo, hi);
        sG[(2 * q + 0) * 152 + c] = lo;
        sG[(2 * q + 1) * 152 + c] = hi;
    }
    __syncthreads();

    // ---------- pair build: Xhi/Xlo[p][c] = split(relu(g_i - g_j + b1)) ----------
    {
        const int cg = tid >> 5;          // warp -> col group of 8
        const int rg = tid & 31;          // row pair 2rg, 2rg+1
        const int c0 = cg * 8;
        float v[2][8];
#pragma unroll
        for (int r = 0; r < 2; r++) {
            int p = 2 * rg + r;
            int i = p >> 3, j = p & 7;
            float4 ga0 = *(const float4*)(sG + i * 152 + c0);
            float4 ga1 = *(const float4*)(sG + i * 152 + c0 + 4);
            float4 gb0 = *(const float4*)(sG + j * 152 + c0);
            float4 gb1 = *(const float4*)(sG + j * 152 + c0 + 4);
            float4 ba  = *(const float4*)(sB1 + c0);
            float4 bb  = *(const float4*)(sB1 + c0 + 4);
            v[r][0] = fmaxf(ga0.x - gb0.x + ba.x, 0.f);
            v[r][1] = fmaxf(ga0.y - gb0.y + ba.y, 0.f);
            v[r][2] = fmaxf(ga0.z - gb0.z + ba.z, 0.f);
            v[r][3] = fmaxf(ga0.w - gb0.w + ba.w, 0.f);
            v[r][4] = fmaxf(ga1.x - gb1.x + bb.x, 0.f);
            v[r][5] = fmaxf(ga1.y - gb1.y + bb.y, 0.f);
            v[r][6] = fmaxf(ga1.z - gb1.z + bb.z, 0.f);
            v[r][7] = fmaxf(ga1.w - gb1.w + bb.w, 0.f);
            if (cg == 18) { v[r][6] = 0.f; v[r][7] = 0.f; }   // cols 150,151 pad
        }
#pragma unroll
        for (int r = 0; r < 2; r++) {
            int p = 2 * rg + r;
#pragma unroll
            for (int jj = 0; jj < 4; jj++) {
                float x0 = v[r][2 * jj], x1 = v[r][2 * jj + 1];
                unsigned short h0 = f2bf(x0), h1 = f2bf(x1);
                float l0 = x0 - bf2f(h0), l1 = x1 - bf2f(h1);
                uint32_t off = (uint32_t)(p * 152 + c0 + 2 * jj) * 2u;
                sts_u32(sb + O_X   + off, (uint32_t)h0 | ((uint32_t)h1 << 16));
                sts_u32(sb + O_XLO + off, pack_bf2(l0, l1));
            }
        }
    }
    __syncthreads();

    // ---------- tensor-core pair GEMMs ----------
    const int lane = tid & 31;
    const int g    = lane >> 2;           // 0..7
    const int tg   = lane & 3;            // 0..3
    const int n0   = (tid >> 5) * 8;      // warp's n8 tile
    const int cc0  = n0 + 2 * tg;         // this thread's output cols cc0, cc0+1

    float acc[4][4];

#pragma unroll 1
    for (int L = 0; L < 2; L++) {
        const uint32_t whb = sb + (L ? O_W2HI : O_WMHI);
        const uint32_t wlb = sb + (L ? O_W2LO : O_WMLO);
        const uint32_t bias_b = sb + (L ? O_B2 : O_BM);
        {
            float bv0 = lds_f32(bias_b + (uint32_t)cc0 * 4u);
            float bv1 = lds_f32(bias_b + (uint32_t)(cc0 + 1) * 4u);
#pragma unroll
            for (int mt = 0; mt < 4; mt++) {
                acc[mt][0] = bv0; acc[mt][1] = bv1;
                acc[mt][2] = bv0; acc[mt][3] = bv1;
            }
        }
        const uint32_t brow = whb + (uint32_t)((n0 + g) * 304);
        const uint32_t brol = wlb + (uint32_t)((n0 + g) * 304);
#pragma unroll 1
        for (int ks = 0; ks < 19; ks++) {
            const uint32_t kb = (uint32_t)(ks * 16 + tg * 4);
            uint32_t bh = lds_u32(brow + kb);
            uint32_t bl = lds_u32(brol + kb);
#pragma unroll
            for (int mt = 0; mt < 4; mt++) {
                uint32_t r0off = (uint32_t)((mt * 16 + g) * 304) + kb;
                uint32_t r1off = r0off + 8u * 304u;
                uint32_t ah0 = lds_u32(sb + O_X   + r0off);
                uint32_t ah1 = lds_u32(sb + O_X   + r1off);
                uint32_t al0 = lds_u32(sb + O_XLO + r0off);
                uint32_t al1 = lds_u32(sb + O_XLO + r1off);
                mma8(acc[mt], ah0, ah1, bh);
                mma8(acc[mt], ah0, ah1, bl);
                mma8(acc[mt], al0, al1, bh);
            }
        }
        __syncthreads();                  // all X reads for this layer done

        if (L == 0) {
            // y = relu(acc) -> re-split into Xhi/Xlo (layer-2 input)
#pragma unroll
            for (int mt = 0; mt < 4; mt++) {
                int r0 = mt * 16 + g, r1 = r0 + 8;
                float y00 = fmaxf(acc[mt][0], 0.f), y01 = fmaxf(acc[mt][1], 0.f);
                float y10 = fmaxf(acc[mt][2], 0.f), y11 = fmaxf(acc[mt][3], 0.f);
                unsigned short h00 = f2bf(y00), h01 = f2bf(y01);
                unsigned short h10 = f2bf(y10), h11 = f2bf(y11);
                uint32_t o0 = (uint32_t)(r0 * 152 + cc0) * 2u;
                uint32_t o1 = (uint32_t)(r1 * 152 + cc0) * 2u;
                sts_u32(sb + O_X   + o0, (uint32_t)h00 | ((uint32_t)h01 << 16));
                sts_u32(sb + O_X   + o1, (uint32_t)h10 | ((uint32_t)h11 << 16));
                sts_u32(sb + O_XLO + o0, pack_bf2(y00 - bf2f(h00), y01 - bf2f(h01)));
                sts_u32(sb + O_XLO + o1, pack_bf2(y10 - bf2f(h10), y11 - bf2f(h11)));
            }
            __syncthreads();
        }
    }

    // ---------- output: out[p][b][cc0..cc0+1] ----------
    if (cc0 < C_) {                       // warp 18, tg=3 -> col 150: skip
#pragma unroll
        for (int mt = 0; mt < 4; mt++) {
            int p0 = mt * 16 + g, p1 = p0 + 8;
            float* o0 = out + ((size_t)p0 * B_ + b) * C_ + cc0;
            float* o1 = out + ((size_t)p1 * B_ + b) * C_ + cc0;
            *(float2*)o0 = make_float2(acc[mt][0], acc[mt][1]);
            *(float2*)o1 = make_float2(acc[mt][2], acc[mt][3]);
        }
    }
}

extern "C" void kernel_launch(void* const* d_in, const int* in_sizes, int n_in,
                              void* d_out, int out_size)
{
    const int*   ids  = (const int*)d_in[0];
    const float* feat = (const float*)d_in[1];
    const float* W1 = (const float*)d_in[2];
    const float* b1 = (const float*)d_in[3];
    const float* Wm = (const float*)d_in[4];
    const float* bm = (const float*)d_in[5];
    const float* W2 = (const float*)d_in[6];
    const float* b2 = (const float*)d_in[7];
    float* out = (float*)d_out;

    cudaFuncSetAttribute(grapher_kernel,
                         cudaFuncAttributeMaxDynamicSharedMemorySize, SMEM_BYTES);
    grapher_kernel<<<B_, NTHR, SMEM_BYTES>>>(ids, feat, W1, b1, Wm, bm, W2, b2, out);
}

// round 12
// speedup vs baseline: 1.6708x; 1.1530x over previous
#include <cuda_runtime.h>
#include <cuda_bf16.h>
#include <cstdint>

// Grapher round 12:
//  Pre-kernel: Wm/W2 fp32 -> bf16 hi/lo, transposed [n][k], written ONCE to a
//    global image byte-matching the main kernel's smem weight block.
//  Main kernel (128 blocks x 608): cp.async the weight image (overlapped with
//    scan/means/GEMM1/pair-build), fp32 means + GEMM1, pair build, then
//    tensor-core pair GEMMs using m16n8k16 (9 steps) + m16n8k8 tail,
//    3-term hi/lo split for fp32-grade accuracy.

#define B_   128
#define S_   1024
#define H_   768
#define C_   150
#define NN   8
#define SEPID 3
#define NTHR 608          // 19 warps

// ---- shared memory byte offsets (weight block contiguous & image-matched) ----
#define O_WMHI 0          // [152][152] bf16 = 46208 B  (Wm^T hi)
#define O_WMLO 46208
#define O_W2HI 92416
#define O_W2LO 138624
#define O_X    184832     // Xhi bf16 [64][152] = 19456 B ; fp32 scratch earlier
#define O_XLO  204288     // Xlo bf16 [64][152]
#define O_SG   223744     // g fp32 [8][152] = 4864 B
#define O_B1   228608     // 152 f32
#define O_BM   229216
#define O_B2   229824
#define O_BND  230432     // 16 int
#define SMEM_BYTES 230496

#define W_IMG_HALF 23104          // 152*152 ushorts per region
typedef unsigned long long u64;

// global weight image: order = WMHI, WMLO, W2HI, W2LO (matches smem block)
__device__ __align__(16) unsigned short g_Wcvt[4 * W_IMG_HALF];

__device__ __forceinline__ uint32_t sptr(const void* p) {
    return (uint32_t)__cvta_generic_to_shared(p);
}
__device__ __forceinline__ void cp16(uint32_t s, const void* g) {
    asm volatile("cp.async.ca.shared.global [%0], [%1], 16;" :: "r"(s), "l"(g));
}
#define CP_COMMIT() asm volatile("cp.async.commit_group;" ::: "memory")
#define CP_WAIT0()  asm volatile("cp.async.wait_group 0;" ::: "memory")

__device__ __forceinline__ void ffma2(u64& d, u64 a, u64 b) {
    asm("fma.rn.f32x2 %0, %1, %2, %0;" : "+l"(d) : "l"(a), "l"(b));
}
__device__ __forceinline__ u64 add2(u64 a, u64 b) {
    u64 r; asm("add.rn.f32x2 %0, %1, %2;" : "=l"(r) : "l"(a), "l"(b)); return r;
}
__device__ __forceinline__ u64 dup2(float x) {
    u64 r; asm("mov.b64 %0, {%1, %1};" : "=l"(r) : "f"(x)); return r;
}
__device__ __forceinline__ void unpack2(u64 v, float& lo, float& hi) {
    asm("mov.b64 {%0, %1}, %2;" : "=f"(lo), "=f"(hi) : "l"(v));
}
__device__ __forceinline__ u64 lds64(uint32_t a) {
    u64 v; asm volatile("ld.shared.u64 %0, [%1];" : "=l"(v) : "r"(a)); return v;
}
__device__ __forceinline__ void lds_v2(uint32_t a, u64& x, u64& y) {
    asm volatile("ld.shared.v2.u64 {%0, %1}, [%2];" : "=l"(x), "=l"(y) : "r"(a));
}
__device__ __forceinline__ void sts64(uint32_t a, u64 v) {
    asm volatile("st.shared.u64 [%0], %1;" :: "r"(a), "l"(v) : "memory");
}
__device__ __forceinline__ uint32_t lds_u32(uint32_t a) {
    uint32_t v; asm volatile("ld.shared.b32 %0, [%1];" : "=r"(v) : "r"(a)); return v;
}
__device__ __forceinline__ void sts_u32(uint32_t a, uint32_t v) {
    asm volatile("st.shared.b32 [%0], %1;" :: "r"(a), "r"(v) : "memory");
}
__device__ __forceinline__ float lds_f32(uint32_t a) {
    float v; asm volatile("ld.shared.f32 %0, [%1];" : "=f"(v) : "r"(a)); return v;
}
__device__ __forceinline__ unsigned short f2bf(float x) {
    __nv_bfloat16 h = __float2bfloat16_rn(x);
    return *reinterpret_cast<unsigned short*>(&h);
}
__device__ __forceinline__ float bf2f(unsigned short u) {
    __nv_bfloat16 h = *reinterpret_cast<__nv_bfloat16*>(&u);
    return __bfloat162float(h);
}
__device__ __forceinline__ uint32_t pack_bf2(float a, float b) {
    return (uint32_t)f2bf(a) | ((uint32_t)f2bf(b) << 16);
}

// D(16x8) += A(16x8)*B(8x8), bf16 in / fp32 accum
__device__ __forceinline__ void mma8(float c[4], uint32_t a0, uint32_t a1, uint32_t b0) {
    asm volatile(
        "mma.sync.aligned.m16n8k8.row.col.f32.bf16.bf16.f32 "
        "{%0,%1,%2,%3}, {%4,%5}, {%6}, {%0,%1,%2,%3};"
        : "+f"(c[0]), "+f"(c[1]), "+f"(c[2]), "+f"(c[3])
        : "r"(a0), "r"(a1), "r"(b0));
}
// D(16x8) += A(16x16)*B(16x8), bf16 in / fp32 accum (full-rate shape)
__device__ __forceinline__ void mma16(float c[4], uint32_t a0, uint32_t a1,
                                      uint32_t a2, uint32_t a3,
                                      uint32_t b0, uint32_t b1) {
    asm volatile(
        "mma.sync.aligned.m16n8k16.row.col.f32.bf16.bf16.f32 "
        "{%0,%1,%2,%3}, {%4,%5,%6,%7}, {%8,%9}, {%0,%1,%2,%3};"
        : "+f"(c[0]), "+f"(c[1]), "+f"(c[2]), "+f"(c[3])
        : "r"(a0), "r"(a1), "r"(a2), "r"(a3), "r"(b0), "r"(b1));
}

// =======================================================================
// pre-kernel: convert Wm/W2 -> transposed bf16 hi/lo global image
// grid 304 = 2 layers x 152 n-rows; 160 threads (k = tid, pad zeroed)
// =======================================================================
__global__ void grapher_cvt(const float* __restrict__ Wm,
                            const float* __restrict__ W2)
{
    const int layer = blockIdx.x / 152;
    const int n     = blockIdx.x - layer * 152;
    const int k     = threadIdx.x;
    if (k >= 152) return;
    const float* src = layer ? W2 : Wm;
    float v = (k < C_ && n < C_) ? __ldg(src + k * C_ + n) : 0.f;
    unsigned short h = f2bf(v);
    unsigned short l = f2bf(v - bf2f(h));
    const int base = layer * 2 * W_IMG_HALF;
    g_Wcvt[base + n * 152 + k] = h;                    // hi region
    g_Wcvt[base + W_IMG_HALF + n * 152 + k] = l;       // lo region
}

// =======================================================================
// main kernel
// =======================================================================
__global__ __launch_bounds__(NTHR, 1)
void grapher_kernel(const int* __restrict__ ids,
                    const float* __restrict__ feat,
                    const float* __restrict__ W1, const float* __restrict__ b1,
                    const float* __restrict__ bm, const float* __restrict__ b2,
                    float* __restrict__ out)
{
    extern __shared__ char smc[];
    const uint32_t sb = sptr(smc);
    float* sG  = (float*)(smc + O_SG);
    float* sB1 = (float*)(smc + O_B1);
    int*   sBnd = (int*)(smc + O_BND);
    float* sX32 = (float*)(smc + O_X);     // fp32 scratch phase (means/GEMM1)

    const int tid = threadIdx.x;
    const int b   = blockIdx.x;
    const uint32_t x_b = sb + O_X;

    // ---------- weight image -> smem via cp.async (drains under phases 1-4) ----
    {
        const uint4* wsrc = (const uint4*)g_Wcvt;
        for (int i = tid; i < 11552; i += NTHR)        // 184832 B / 16
            cp16(sb + O_WMHI + (uint32_t)i * 16u, wsrc + i);
        CP_COMMIT();
    }

    // ---------- phase 1: separator scan (warp 0) + bias loads ----------
    if (tid < 32) {
        const int lane = tid;
        if (lane < 16) sBnd[lane] = S_;
        __syncwarp();
        const int4* rp = (const int4*)(ids + (size_t)b * S_) + lane * 8;
        int4 v[8];
        int cnt = 0;
#pragma unroll
        for (int q = 0; q < 8; q++) {
            v[q] = rp[q];
            cnt += (v[q].x == SEPID) + (v[q].y == SEPID) +
                   (v[q].z == SEPID) + (v[q].w == SEPID);
        }
        int pre = cnt;
#pragma unroll
        for (int off = 1; off < 32; off <<= 1) {
            int t = __shfl_up_sync(0xffffffffu, pre, off);
            if (lane >= off) pre += t;
        }
        int run = pre - cnt;
#pragma unroll
        for (int q = 0; q < 8; q++) {
            int base = lane * 32 + q * 4;
            if (v[q].x == SEPID) { run++; if (run <= NN) sBnd[run] = base + 0; }
            if (v[q].y == SEPID) { run++; if (run <= NN) sBnd[run] = base + 1; }
            if (v[q].z == SEPID) { run++; if (run <= NN) sBnd[run] = base + 2; }
            if (v[q].w == SEPID) { run++; if (run <= NN) sBnd[run] = base + 3; }
        }
    } else if (tid >= 448 && tid < 448 + 152) {
        int i = tid - 448;
        sB1[i] = (i < C_) ? b1[i] : 0.f;
        ((float*)(smc + O_BM))[i] = (i < C_) ? bm[i] : 0.f;
        ((float*)(smc + O_B2))[i] = (i < C_) ? b2[i] : 0.f;
    }
    __syncthreads();

    // ---------- phase 2: means (tid<384) || W1 L2-prefetch (spares) ----------
    if (tid < 384) {
        const float2* f2 = (const float2*)(feat + (size_t)b * S_ * H_) + tid;
#pragma unroll 1
        for (int n = 0; n < NN; n++) {
            int lo = (n == 0) ? 0 : sBnd[n] + 1;
            int hi = sBnd[n + 1];
            float2 a0 = make_float2(0.f, 0.f), a1 = a0, a2 = a0, a3 = a0;
            int t = lo;
            for (; t + 3 < hi; t += 4) {
                float2 v0 = f2[(t + 0) * 384];
                float2 v1 = f2[(t + 1) * 384];
                float2 v2 = f2[(t + 2) * 384];
                float2 v3 = f2[(t + 3) * 384];
                a0.x += v0.x; a0.y += v0.y;
                a1.x += v1.x; a1.y += v1.y;
                a2.x += v2.x; a2.y += v2.y;
                a3.x += v3.x; a3.y += v3.y;
            }
            for (; t < hi; t++) {
                float2 v = f2[t * 384];
                a0.x += v.x; a0.y += v.y;
            }
            float sx = (a0.x + a1.x) + (a2.x + a3.x);
            float sy = (a0.y + a1.y) + (a2.y + a3.y);
            int c = hi - lo; if (c < 1) c = 1;
            float inv = 1.0f / (float)c;
            sX32[(2 * tid + 0) * 8 + n] = sx * inv;
            sX32[(2 * tid + 1) * 8 + n] = sy * inv;
        }
    } else {
        const float4* w4 = (const float4*)W1;
        for (int i = tid - 384; i < (H_ * C_) / 4; i += 224)
            asm volatile("prefetch.global.L2 [%0];" :: "l"(w4 + i));
    }
    __syncthreads();

    // ---------- GEMM1 (fp32 FFMA2): g[n][c] = sum_k meansT[k][n]*W1[k][c] ----
    u64 g_acc[2][4];
    int ks1 = 0, cpair = 0;
    if (tid < 600) {
        ks1 = tid / 75; cpair = tid - ks1 * 75;
#pragma unroll
        for (int cc = 0; cc < 2; cc++)
#pragma unroll
            for (int q = 0; q < 4; q++) g_acc[cc][q] = 0ull;
        const float2* wrow = (const float2*)(W1 + (size_t)(ks1 * 96) * C_) + cpair;
#pragma unroll 4
        for (int kk = 0; kk < 96; kk++) {
            int k = ks1 * 96 + kk;
            float2 w = __ldg(wrow + kk * 75);
            u64 dw0 = dup2(w.x), dw1 = dup2(w.y);
            u64 m01, m23, m45, m67;
            uint32_t ma = x_b + (uint32_t)(k * 8) * 4u;
            lds_v2(ma, m01, m23);
            lds_v2(ma + 16u, m45, m67);
            ffma2(g_acc[0][0], m01, dw0); ffma2(g_acc[0][1], m23, dw0);
            ffma2(g_acc[0][2], m45, dw0); ffma2(g_acc[0][3], m67, dw0);
            ffma2(g_acc[1][0], m01, dw1); ffma2(g_acc[1][1], m23, dw1);
            ffma2(g_acc[1][2], m45, dw1); ffma2(g_acc[1][3], m67, dw1);
        }
    }
    __syncthreads();
    if (tid < 600) {
#pragma unroll
        for (int cc = 0; cc < 2; cc++)
#pragma unroll
            for (int q = 0; q < 4; q++)
                sts64(x_b + (uint32_t)(ks1 * 1200 + (cc * 4 + q) * 150 + 2 * cpair) * 4u,
                      g_acc[cc][q]);
    }
    __syncthreads();
    if (tid < 600) {
        u64 s = lds64(x_b + (uint32_t)(2 * tid) * 4u);
#pragma unroll
        for (int k8 = 1; k8 < 8; k8++)
            s = add2(s, lds64(x_b + (uint32_t)(k8 * 1200 + 2 * tid) * 4u));
        int e = tid / 75, cp2 = tid - e * 75;
        int cc = e >> 2, q = e & 3, c = 2 * cp2 + cc;
        float lo, hi; unpack2(s, lo, hi);
        sG[(2 * q + 0) * 152 + c] = lo;
        sG[(2 * q + 1) * 152 + c] = hi;
    }
    __syncthreads();

    // ---------- pair build: Xhi/Xlo[p][c] = split(relu(g_i - g_j + b1)) ------
    {
        const int cg = tid >> 5;
        const int rg = tid & 31;
        const int c0 = cg * 8;
        float v[2][8];
#pragma unroll
        for (int r = 0; r < 2; r++) {
            int p = 2 * rg + r;
            int i = p >> 3, j = p & 7;
            float4 ga0 = *(const float4*)(sG + i * 152 + c0);
            float4 ga1 = *(const float4*)(sG + i * 152 + c0 + 4);
            float4 gb0 = *(const float4*)(sG + j * 152 + c0);
            float4 gb1 = *(const float4*)(sG + j * 152 + c0 + 4);
            float4 ba  = *(const float4*)(sB1 + c0);
            float4 bb  = *(const float4*)(sB1 + c0 + 4);
            v[r][0] = fmaxf(ga0.x - gb0.x + ba.x, 0.f);
            v[r][1] = fmaxf(ga0.y - gb0.y + ba.y, 0.f);
            v[r][2] = fmaxf(ga0.z - gb0.z + ba.z, 0.f);
            v[r][3] = fmaxf(ga0.w - gb0.w + ba.w, 0.f);
            v[r][4] = fmaxf(ga1.x - gb1.x + bb.x, 0.f);
            v[r][5] = fmaxf(ga1.y - gb1.y + bb.y, 0.f);
            v[r][6] = fmaxf(ga1.z - gb1.z + bb.z, 0.f);
            v[r][7] = fmaxf(ga1.w - gb1.w + bb.w, 0.f);
            if (cg == 18) { v[r][6] = 0.f; v[r][7] = 0.f; }   // pad cols 150,151
        }
#pragma unroll
        for (int r = 0; r < 2; r++) {
            int p = 2 * rg + r;
#pragma unroll
            for (int jj = 0; jj < 4; jj++) {
                float x0 = v[r][2 * jj], x1 = v[r][2 * jj + 1];
                unsigned short h0 = f2bf(x0), h1 = f2bf(x1);
                float l0 = x0 - bf2f(h0), l1 = x1 - bf2f(h1);
                uint32_t off = (uint32_t)(p * 152 + c0 + 2 * jj) * 2u;
                sts_u32(sb + O_X   + off, (uint32_t)h0 | ((uint32_t)h1 << 16));
                sts_u32(sb + O_XLO + off, pack_bf2(l0, l1));
            }
        }
    }
    CP_WAIT0();                           // weight image resident
    __syncthreads();

    // ---------- tensor-core pair GEMMs: 9x m16n8k16 + 1x m16n8k8 tail -------
    const int lane = tid & 31;
    const int g    = lane >> 2;           // 0..7
    const int tg   = lane & 3;            // 0..3
    const int n0   = (tid >> 5) * 8;      // warp's n8 tile
    const int cc0  = n0 + 2 * tg;

    float acc[4][4];

#pragma unroll 1
    for (int L = 0; L < 2; L++) {
        const uint32_t whb = sb + (L ? O_W2HI : O_WMHI);
        const uint32_t wlb = sb + (L ? O_W2LO : O_WMLO);
        const uint32_t bias_b = sb + (L ? O_B2 : O_BM);
        {
            float bv0 = lds_f32(bias_b + (uint32_t)cc0 * 4u);
            float bv1 = lds_f32(bias_b + (uint32_t)(cc0 + 1) * 4u);
#pragma unroll
            for (int mt = 0; mt < 4; mt++) {
                acc[mt][0] = bv0; acc[mt][1] = bv1;
                acc[mt][2] = bv0; acc[mt][3] = bv1;
            }
        }
        const uint32_t brow = whb + (uint32_t)((n0 + g) * 304);
        const uint32_t brol = wlb + (uint32_t)((n0 + g) * 304);

#pragma unroll 1
        for (int ks = 0; ks < 9; ks++) {              // k = 16*ks .. +15
            const uint32_t kb = (uint32_t)(ks * 32 + tg * 4);
            uint32_t bh0 = lds_u32(brow + kb);
            uint32_t bh1 = lds_u32(brow + kb + 16u);
            uint32_t bl0 = lds_u32(brol + kb);
            uint32_t bl1 = lds_u32(brol + kb + 16u);
#pragma unroll
            for (int mt = 0; mt < 4; mt++) {
                uint32_t r0off = (uint32_t)((mt * 16 + g) * 304) + kb;
                uint32_t r1off = r0off + 8u * 304u;
                uint32_t ah0 = lds_u32(sb + O_X + r0off);
                uint32_t ah1 = lds_u32(sb + O_X + r1off);
                uint32_t ah2 = lds_u32(sb + O_X + r0off + 16u);
                uint32_t ah3 = lds_u32(sb + O_X + r1off + 16u);
                uint32_t al0 = lds_u32(sb + O_XLO + r0off);
                uint32_t al1 = lds_u32(sb + O_XLO + r1off);
                uint32_t al2 = lds_u32(sb + O_XLO + r0off + 16u);
                uint32_t al3 = lds_u32(sb + O_XLO + r1off + 16u);
                mma16(acc[mt], ah0, ah1, ah2, ah3, bh0, bh1);
                mma16(acc[mt], ah0, ah1, ah2, ah3, bl0, bl1);
                mma16(acc[mt], al0, al1, al2, al3, bh0, bh1);
            }
        }
        {                                              // k8 tail: k = 144..151
            const uint32_t kb = (uint32_t)(288 + tg * 4);
            uint32_t bh = lds_u32(brow + kb);
            uint32_t bl = lds_u32(brol + kb);
#pragma unroll
            for (int mt = 0; mt < 4; mt++) {
                uint32_t r0off = (uint32_t)((mt * 16 + g) * 304) + kb;
                uint32_t r1off = r0off + 8u * 304u;
                uint32_t ah0 = lds_u32(sb + O_X + r0off);
                uint32_t ah1 = lds_u32(sb + O_X + r1off);
                uint32_t al0 = lds_u32(sb + O_XLO + r0off);
                uint32_t al1 = lds_u32(sb + O_XLO + r1off);
                mma8(acc[mt], ah0, ah1, bh);
                mma8(acc[mt], ah0, ah1, bl);
                mma8(acc[mt], al0, al1, bh);
            }
        }
        __syncthreads();                  // all X reads for this layer done

        if (L == 0) {
            // y = relu(acc) -> re-split into Xhi/Xlo (layer-2 input)
#pragma unroll
            for (int mt = 0; mt < 4; mt++) {
                int r0 = mt * 16 + g, r1 = r0 + 8;
                float y00 = fmaxf(acc[mt][0], 0.f), y01 = fmaxf(acc[mt][1], 0.f);
                float y10 = fmaxf(acc[mt][2], 0.f), y11 = fmaxf(acc[mt][3], 0.f);
                unsigned short h00 = f2bf(y00), h01 = f2bf(y01);
                unsigned short h10 = f2bf(y10), h11 = f2bf(y11);
                uint32_t o0 = (uint32_t)(r0 * 152 + cc0) * 2u;
                uint32_t o1 = (uint32_t)(r1 * 152 + cc0) * 2u;
                sts_u32(sb + O_X   + o0, (uint32_t)h00 | ((uint32_t)h01 << 16));
                sts_u32(sb + O_X   + o1, (uint32_t)h10 | ((uint32_t)h11 << 16));
                sts_u32(sb + O_XLO + o0, pack_bf2(y00 - bf2f(h00), y01 - bf2f(h01)));
                sts_u32(sb + O_XLO + o1, pack_bf2(y10 - bf2f(h10), y11 - bf2f(h11)));
            }
            __syncthreads();
        }
    }

    // ---------- output ----------
    if (cc0 < C_) {
#pragma unroll
        for (int mt = 0; mt < 4; mt++) {
            int p0 = mt * 16 + g, p1 = p0 + 8;
            float* o0 = out + ((size_t)p0 * B_ + b) * C_ + cc0;
            float* o1 = out + ((size_t)p1 * B_ + b) * C_ + cc0;
            *(float2*)o0 = make_float2(acc[mt][0], acc[mt][1]);
            *(float2*)o1 = make_float2(acc[mt][2], acc[mt][3]);
        }
    }
}

extern "C" void kernel_launch(void* const* d_in, const int* in_sizes, int n_in,
                              void* d_out, int out_size)
{
    const int*   ids  = (const int*)d_in[0];
    const float* feat = (const float*)d_in[1];
    const float* W1 = (const float*)d_in[2];
    const float* b1 = (const float*)d_in[3];
    const float* Wm = (const float*)d_in[4];
    const float* bm = (const float*)d_in[5];
    const float* W2 = (const float*)d_in[6];
    const float* b2 = (const float*)d_in[7];
    float* out = (float*)d_out;

    cudaFuncSetAttribute(grapher_kernel,
                         cudaFuncAttributeMaxDynamicSharedMemorySize, SMEM_BYTES);

    grapher_cvt<<<304, 160>>>(Wm, W2);
    grapher_kernel<<<B_, NTHR, SMEM_BYTES>>>(ids, feat, W1, b1, bm, b2, out);
}

// round 14
// speedup vs baseline: 1.6891x; 1.0109x over previous
#include <cuda_runtime.h>
#include <cuda_bf16.h>
#include <cstdint>

// Grapher round 14 (= R13 resubmitted after infra failure), three launches:
//  cvt: Wm/W2 fp32 -> bf16 hi/lo transposed global image (once).
//  K1 (128 x 1024): scan + means + GEMM1 (mean@W1, fp32) + pair build, emitting
//     X = relu(g_i-g_j+b1) as bf16 hi/lo DIRECTLY to a global image that
//     byte-matches K2's smem X block.
//  K2 (128 x 608): cp.async Wm+X (group A) and W2 (group B, drains under
//     layer 1), then the R12 tensor-core 2-layer MLP (m16n8k16 + k8 tail,
//     3-term hi/lo split).

#define B_   128
#define S_   1024
#define H_   768
#define C_   150
#define NN   8
#define SEPID 3

typedef unsigned long long u64;

#define W_IMG_HALF 23104          // 152*152 ushorts per region

// global weight image: WMHI, WMLO, W2HI, W2LO (matches K2 smem block)
__device__ __align__(16) unsigned short g_Wcvt[4 * W_IMG_HALF];
// global X image per batch: Xhi[64][152] then Xlo[64][152] bf16 (9728 u32 / batch)
__device__ __align__(16) uint32_t g_Ximg[B_ * 9728];

// ---------------- helpers ----------------
__device__ __forceinline__ uint32_t sptr(const void* p) {
    return (uint32_t)__cvta_generic_to_shared(p);
}
__device__ __forceinline__ void cp16(uint32_t s, const void* g) {
    asm volatile("cp.async.ca.shared.global [%0], [%1], 16;" :: "r"(s), "l"(g));
}
#define CP_COMMIT() asm volatile("cp.async.commit_group;" ::: "memory")
#define CP_WAIT1()  asm volatile("cp.async.wait_group 1;" ::: "memory")
#define CP_WAIT0()  asm volatile("cp.async.wait_group 0;" ::: "memory")

__device__ __forceinline__ void ffma2(u64& d, u64 a, u64 b) {
    asm("fma.rn.f32x2 %0, %1, %2, %0;" : "+l"(d) : "l"(a), "l"(b));
}
__device__ __forceinline__ u64 add2(u64 a, u64 b) {
    u64 r; asm("add.rn.f32x2 %0, %1, %2;" : "=l"(r) : "l"(a), "l"(b)); return r;
}
__device__ __forceinline__ u64 dup2(float x) {
    u64 r; asm("mov.b64 %0, {%1, %1};" : "=l"(r) : "f"(x)); return r;
}
__device__ __forceinline__ void unpack2(u64 v, float& lo, float& hi) {
    asm("mov.b64 {%0, %1}, %2;" : "=f"(lo), "=f"(hi) : "l"(v));
}
__device__ __forceinline__ u64 lds64(uint32_t a) {
    u64 v; asm volatile("ld.shared.u64 %0, [%1];" : "=l"(v) : "r"(a)); return v;
}
__device__ __forceinline__ void lds_v2(uint32_t a, u64& x, u64& y) {
    asm volatile("ld.shared.v2.u64 {%0, %1}, [%2];" : "=l"(x), "=l"(y) : "r"(a));
}
__device__ __forceinline__ void sts64(uint32_t a, u64 v) {
    asm volatile("st.shared.u64 [%0], %1;" :: "r"(a), "l"(v) : "memory");
}
__device__ __forceinline__ uint32_t lds_u32(uint32_t a) {
    uint32_t v; asm volatile("ld.shared.b32 %0, [%1];" : "=r"(v) : "r"(a)); return v;
}
__device__ __forceinline__ void sts_u32(uint32_t a, uint32_t v) {
    asm volatile("st.shared.b32 [%0], %1;" :: "r"(a), "r"(v) : "memory");
}
__device__ __forceinline__ unsigned short f2bf(float x) {
    __nv_bfloat16 h = __float2bfloat16_rn(x);
    return *reinterpret_cast<unsigned short*>(&h);
}
__device__ __forceinline__ float bf2f(unsigned short u) {
    __nv_bfloat16 h = *reinterpret_cast<__nv_bfloat16*>(&u);
    return __bfloat162float(h);
}
__device__ __forceinline__ uint32_t pack_bf2(float a, float b) {
    return (uint32_t)f2bf(a) | ((uint32_t)f2bf(b) << 16);
}

__device__ __forceinline__ void mma8(float c[4], uint32_t a0, uint32_t a1, uint32_t b0) {
    asm volatile(
        "mma.sync.aligned.m16n8k8.row.col.f32.bf16.bf16.f32 "
        "{%0,%1,%2,%3}, {%4,%5}, {%6}, {%0,%1,%2,%3};"
        : "+f"(c[0]), "+f"(c[1]), "+f"(c[2]), "+f"(c[3])
        : "r"(a0), "r"(a1), "r"(b0));
}
__device__ __forceinline__ void mma16(float c[4], uint32_t a0, uint32_t a1,
                                      uint32_t a2, uint32_t a3,
                                      uint32_t b0, uint32_t b1) {
    asm volatile(
        "mma.sync.aligned.m16n8k16.row.col.f32.bf16.bf16.f32 "
        "{%0,%1,%2,%3}, {%4,%5,%6,%7}, {%8,%9}, {%0,%1,%2,%3};"
        : "+f"(c[0]), "+f"(c[1]), "+f"(c[2]), "+f"(c[3])
        : "r"(a0), "r"(a1), "r"(a2), "r"(a3), "r"(b0), "r"(b1));
}

// =======================================================================
// cvt: Wm/W2 -> transposed bf16 hi/lo image (once)
// =======================================================================
__global__ void grapher_cvt(const float* __restrict__ Wm,
                            const float* __restrict__ W2)
{
    const int layer = blockIdx.x / 152;
    const int n     = blockIdx.x - layer * 152;
    const int k     = threadIdx.x;
    if (k >= 152) return;
    const float* src = layer ? W2 : Wm;
    float v = (k < C_ && n < C_) ? __ldg(src + k * C_ + n) : 0.f;
    unsigned short h = f2bf(v);
    unsigned short l = f2bf(v - bf2f(h));
    const int base = layer * 2 * W_IMG_HALF;
    g_Wcvt[base + n * 152 + k] = h;
    g_Wcvt[base + W_IMG_HALF + n * 152 + k] = l;
}

// =======================================================================
// K1 : scan + means + GEMM1 + pair build -> g_Ximg (bf16 hi/lo)
// =======================================================================
#define NT1 1024
#define OFF_P   0                 // means partials P[5][8][772]=30880; then GEMM1 partials
#define OFF_MT  30880             // meansT[768][8] = 6144
#define OFF_G   37024             // 8*152
#define OFF_B1  38240             // 152
#define OFF_BND 38392             // 16 ints
#define SM1_FLOATS 38408
#define SM1_BYTES (SM1_FLOATS * 4)   // 153632

__global__ __launch_bounds__(NT1, 1)
void grapher_k1(const int* __restrict__ ids,
                const float* __restrict__ feat,
                const float* __restrict__ W1, const float* __restrict__ b1)
{
    extern __shared__ float sm[];
    float* sP  = sm + OFF_P;
    float* sMT = sm + OFF_MT;
    float* sG  = sm + OFF_G;
    float* sB1 = sm + OFF_B1;
    int*   sBnd = (int*)(sm + OFF_BND);

    const int tid = threadIdx.x;
    const int b   = blockIdx.x;
    const uint32_t mt_b = sptr(sMT);
    const uint32_t pp_b = sptr(sP);

    // ---- scan (warp 0) + b1 load ----
    if (tid < 32) {
        const int lane = tid;
        if (lane < 16) sBnd[lane] = S_;
        __syncwarp();
        const int4* rp = (const int4*)(ids + (size_t)b * S_) + lane * 8;
        int4 v[8];
        int cnt = 0;
#pragma unroll
        for (int q = 0; q < 8; q++) {
            v[q] = rp[q];
            cnt += (v[q].x == SEPID) + (v[q].y == SEPID) +
                   (v[q].z == SEPID) + (v[q].w == SEPID);
        }
        int pre = cnt;
#pragma unroll
        for (int off = 1; off < 32; off <<= 1) {
            int t = __shfl_up_sync(0xffffffffu, pre, off);
            if (lane >= off) pre += t;
        }
        int run = pre - cnt;
#pragma unroll
        for (int q = 0; q < 8; q++) {
            int base = lane * 32 + q * 4;
            if (v[q].x == SEPID) { run++; if (run <= NN) sBnd[run] = base + 0; }
            if (v[q].y == SEPID) { run++; if (run <= NN) sBnd[run] = base + 1; }
            if (v[q].z == SEPID) { run++; if (run <= NN) sBnd[run] = base + 2; }
            if (v[q].w == SEPID) { run++; if (run <= NN) sBnd[run] = base + 3; }
        }
    } else if (tid >= 64 && tid < 64 + 152) {
        int i = tid - 64;
        sB1[i] = (i < C_) ? b1[i] : 0.f;
    }
    __syncthreads();

    // ---- means partials: 5 contiguous token tiles x 192 float4 cols ----
    if (tid < 960) {
        const int tg  = tid / 192;
        const int col = tid - tg * 192;
        const int T   = sBnd[NN];
        const int tb0 = (T * tg) / 5;
        const int tb1 = (T * (tg + 1)) / 5;
        const float4* f4 = (const float4*)(feat + (size_t)b * S_ * H_) + col;
        float* P = sP + tg * 6176 + col * 4;
#pragma unroll 1
        for (int n = 0; n < NN; n++) {
            int lo = (n == 0) ? 0 : sBnd[n] + 1;
            int hi = sBnd[n + 1];
            if (lo < tb0) lo = tb0;
            if (hi > tb1) hi = tb1;
            float4 a0 = make_float4(0.f, 0.f, 0.f, 0.f), a1 = a0, a2 = a0, a3 = a0;
            int t = lo;
            for (; t + 3 < hi; t += 4) {
                float4 v0 = f4[(t + 0) * 192];
                float4 v1 = f4[(t + 1) * 192];
                float4 v2 = f4[(t + 2) * 192];
                float4 v3 = f4[(t + 3) * 192];
                a0.x += v0.x; a0.y += v0.y; a0.z += v0.z; a0.w += v0.w;
                a1.x += v1.x; a1.y += v1.y; a1.z += v1.z; a1.w += v1.w;
                a2.x += v2.x; a2.y += v2.y; a2.z += v2.z; a2.w += v2.w;
                a3.x += v3.x; a3.y += v3.y; a3.z += v3.z; a3.w += v3.w;
            }
            for (; t < hi; t++) {
                float4 v = f4[t * 192];
                a0.x += v.x; a0.y += v.y; a0.z += v.z; a0.w += v.w;
            }
            float4 s;
            s.x = (a0.x + a1.x) + (a2.x + a3.x);
            s.y = (a0.y + a1.y) + (a2.y + a3.y);
            s.z = (a0.z + a1.z) + (a2.z + a3.z);
            s.w = (a0.w + a1.w) + (a2.w + a3.w);
            *(float4*)(P + n * 772) = s;
        }
    } else {
        // 2 spare warps: L2-prefetch W1 for GEMM1
        const float4* w4 = (const float4*)W1;
        for (int i = tid - 960; i < (H_ * C_) / 4; i += 64)
            asm volatile("prefetch.global.L2 [%0];" :: "l"(w4 + i));
    }
    __syncthreads();

    // ---- combine tiles + 1/len -> meansT[k][8] ----
    if (tid < H_) {
        float inv[8];
#pragma unroll
        for (int n = 0; n < NN; n++) {
            int lo = (n == 0) ? 0 : sBnd[n] + 1;
            int len = sBnd[n + 1] - lo;
            if (len < 1) len = 1;
            inv[n] = 1.0f / (float)len;
        }
        const float* P = sP + tid;
#pragma unroll
        for (int n = 0; n < NN; n++) {
            float s = ((P[n * 772] + P[6176 + n * 772]) +
                       (P[12352 + n * 772] + P[18528 + n * 772])) + P[24704 + n * 772];
            sMT[tid * 8 + n] = s * inv[n];
        }
    }
    __syncthreads();                      // P region free for GEMM1 partials

    // ---- GEMM1 (fp32 FFMA2): g[n][c] = sum_k meansT[k][n] * W1[k][c] ----
    u64 g_acc[2][4];
    int ks1 = 0, cpair = 0;
    if (tid < 600) {
        ks1 = tid / 75; cpair = tid - ks1 * 75;
#pragma unroll
        for (int cc = 0; cc < 2; cc++)
#pragma unroll
            for (int q = 0; q < 4; q++) g_acc[cc][q] = 0ull;
        const float2* wrow = (const float2*)(W1 + (size_t)(ks1 * 96) * C_) + cpair;
#pragma unroll 4
        for (int kk = 0; kk < 96; kk++) {
            int k = ks1 * 96 + kk;
            float2 w = __ldg(wrow + kk * 75);
            u64 dw0 = dup2(w.x), dw1 = dup2(w.y);
            u64 m01, m23, m45, m67;
            uint32_t ma = mt_b + (uint32_t)(k * 8) * 4u;
            lds_v2(ma, m01, m23);
            lds_v2(ma + 16u, m45, m67);
            ffma2(g_acc[0][0], m01, dw0); ffma2(g_acc[0][1], m23, dw0);
            ffma2(g_acc[0][2], m45, dw0); ffma2(g_acc[0][3], m67, dw0);
            ffma2(g_acc[1][0], m01, dw1); ffma2(g_acc[1][1], m23, dw1);
            ffma2(g_acc[1][2], m45, dw1); ffma2(g_acc[1][3], m67, dw1);
        }
    }
    __syncthreads();
    if (tid < 600) {
#pragma unroll
        for (int cc = 0; cc < 2; cc++)
#pragma unroll
            for (int q = 0; q < 4; q++)
                sts64(pp_b + (uint32_t)(ks1 * 1200 + (cc * 4 + q) * 150 + 2 * cpair) * 4u,
                      g_acc[cc][q]);
    }
    __syncthreads();
    if (tid < 600) {
        u64 s = lds64(pp_b + (uint32_t)(2 * tid) * 4u);
#pragma unroll
        for (int k8 = 1; k8 < 8; k8++)
            s = add2(s, lds64(pp_b + (uint32_t)(k8 * 1200 + 2 * tid) * 4u));
        int e = tid / 75, cp2 = tid - e * 75;
        int cc = e >> 2, q = e & 3, c = 2 * cp2 + cc;
        float lo, hi; unpack2(s, lo, hi);
        sG[(2 * q + 0) * 152 + c] = lo;
        sG[(2 * q + 1) * 152 + c] = hi;
    }
    __syncthreads();

    // ---- pair build -> g_Ximg[b]: Xhi then Xlo, bf16, pads zero ----
    {
        const int p  = tid >> 4;          // 0..63
        const int cs = tid & 15;          // 16 col segments of 10
        const int i  = p >> 3, j = p & 7;
        const int c0 = cs * 10;
        uint32_t* dhi = g_Ximg + (size_t)b * 9728 + p * 76;
        uint32_t* dlo = dhi + 4864;
#pragma unroll
        for (int m = 0; m < 5; m++) {
            int c = c0 + 2 * m;
            if (c < 152) {
                float v0 = 0.f, v1 = 0.f;
                if (c < C_)
                    v0 = fmaxf(sG[i * 152 + c] - sG[j * 152 + c] + sB1[c], 0.f);
                if (c + 1 < C_)
                    v1 = fmaxf(sG[i * 152 + c + 1] - sG[j * 152 + c + 1] + sB1[c + 1], 0.f);
                unsigned short h0 = f2bf(v0), h1 = f2bf(v1);
                dhi[c >> 1] = (uint32_t)h0 | ((uint32_t)h1 << 16);
                dlo[c >> 1] = pack_bf2(v0 - bf2f(h0), v1 - bf2f(h1));
            }
        }
    }
}

// =======================================================================
// K2 : tensor-core 2-layer MLP (per batch)
// =======================================================================
#define NT2 608
#define O_WMHI 0
#define O_WMLO 46208
#define O_W2HI 92416
#define O_W2LO 138624
#define O_X    184832     // Xhi bf16 [64][152]
#define O_XLO  204288     // Xlo bf16 [64][152]
#define SM2_BYTES 223744

__global__ __launch_bounds__(NT2, 1)
void grapher_k2(const float* __restrict__ bm, const float* __restrict__ b2,
                float* __restrict__ out)
{
    extern __shared__ char smc[];
    const uint32_t sb = sptr(smc);
    const int tid = threadIdx.x;
    const int b   = blockIdx.x;

    // ---- group A: Wm hi/lo (5776 cp16) + X image (2432 cp16) ----
    {
        const uint4* wsrc = (const uint4*)g_Wcvt;
        const uint4* xsrc = (const uint4*)(g_Ximg + (size_t)b * 9728);
        for (int i = tid; i < 8208; i += NT2) {
            if (i < 5776) cp16(sb + O_WMHI + (uint32_t)i * 16u, wsrc + i);
            else          cp16(sb + O_X + (uint32_t)(i - 5776) * 16u, xsrc + (i - 5776));
        }
        CP_COMMIT();
        // ---- group B: W2 hi/lo (drains under layer 1) ----
        for (int i = tid; i < 5776; i += NT2)
            cp16(sb + O_W2HI + (uint32_t)i * 16u, wsrc + 5776 + i);
        CP_COMMIT();
    }

    const int lane = tid & 31;
    const int g    = lane >> 2;           // 0..7
    const int tg   = lane & 3;            // 0..3
    const int n0   = (tid >> 5) * 8;      // warp's n8 tile
    const int cc0  = n0 + 2 * tg;

    CP_WAIT1();                           // group A resident (Wm + X)
    __syncthreads();

    float acc[4][4];

#pragma unroll 1
    for (int L = 0; L < 2; L++) {
        const uint32_t whb = sb + (L ? O_W2HI : O_WMHI);
        const uint32_t wlb = sb + (L ? O_W2LO : O_WMLO);
        const float* bias = L ? b2 : bm;
        {
            float bv0 = (cc0 < C_)     ? __ldg(bias + cc0)     : 0.f;
            float bv1 = (cc0 + 1 < C_) ? __ldg(bias + cc0 + 1) : 0.f;
#pragma unroll
            for (int mt = 0; mt < 4; mt++) {
                acc[mt][0] = bv0; acc[mt][1] = bv1;
                acc[mt][2] = bv0; acc[mt][3] = bv1;
            }
        }
        const uint32_t brow = whb + (uint32_t)((n0 + g) * 304);
        const uint32_t brol = wlb + (uint32_t)((n0 + g) * 304);

#pragma unroll 1
        for (int ks = 0; ks < 9; ks++) {              // k = 16*ks .. +15
            const uint32_t kb = (uint32_t)(ks * 32 + tg * 4);
            uint32_t bh0 = lds_u32(brow + kb);
            uint32_t bh1 = lds_u32(brow + kb + 16u);
            uint32_t bl0 = lds_u32(brol + kb);
            uint32_t bl1 = lds_u32(brol + kb + 16u);
#pragma unroll
            for (int mt = 0; mt < 4; mt++) {
                uint32_t r0off = (uint32_t)((mt * 16 + g) * 304) + kb;
                uint32_t r1off = r0off + 8u * 304u;
                uint32_t ah0 = lds_u32(sb + O_X + r0off);
                uint32_t ah1 = lds_u32(sb + O_X + r1off);
                uint32_t ah2 = lds_u32(sb + O_X + r0off + 16u);
                uint32_t ah3 = lds_u32(sb + O_X + r1off + 16u);
                uint32_t al0 = lds_u32(sb + O_XLO + r0off);
                uint32_t al1 = lds_u32(sb + O_XLO + r1off);
                uint32_t al2 = lds_u32(sb + O_XLO + r0off + 16u);
                uint32_t al3 = lds_u32(sb + O_XLO + r1off + 16u);
                mma16(acc[mt], ah0, ah1, ah2, ah3, bh0, bh1);
                mma16(acc[mt], ah0, ah1, ah2, ah3, bl0, bl1);
                mma16(acc[mt], al0, al1, al2, al3, bh0, bh1);
            }
        }
        {                                              // k8 tail: k = 144..151
            const uint32_t kb = (uint32_t)(288 + tg * 4);
            uint32_t bh = lds_u32(brow + kb);
            uint32_t bl = lds_u32(brol + kb);
#pragma unroll
            for (int mt = 0; mt < 4; mt++) {
                uint32_t r0off = (uint32_t)((mt * 16 + g) * 304) + kb;
                uint32_t r1off = r0off + 8u * 304u;
                uint32_t ah0 = lds_u32(sb + O_X + r0off);
                uint32_t ah1 = lds_u32(sb + O_X + r1off);
                uint32_t al0 = lds_u32(sb + O_XLO + r0off);
                uint32_t al1 = lds_u32(sb + O_XLO + r1off);
                mma8(acc[mt], ah0, ah1, bh);
                mma8(acc[mt], ah0, ah1, bl);
                mma8(acc[mt], al0, al1, bh);
            }
        }
        __syncthreads();                  // all X reads for this layer done

        if (L == 0) {
            // y = relu(acc) -> re-split into Xhi/Xlo (layer-2 input)
#pragma unroll
            for (int mt = 0; mt < 4; mt++) {
                int r0 = mt * 16 + g, r1 = r0 + 8;
                float y00 = fmaxf(acc[mt][0], 0.f), y01 = fmaxf(acc[mt][1], 0.f);
                float y10 = fmaxf(acc[mt][2], 0.f), y11 = fmaxf(acc[mt][3], 0.f);
                unsigned short h00 = f2bf(y00), h01 = f2bf(y01);
                unsigned short h10 = f2bf(y10), h11 = f2bf(y11);
                uint32_t o0 = (uint32_t)(r0 * 152 + cc0) * 2u;
                uint32_t o1 = (uint32_t)(r1 * 152 + cc0) * 2u;
                sts_u32(sb + O_X   + o0, (uint32_t)h00 | ((uint32_t)h01 << 16));
                sts_u32(sb + O_X   + o1, (uint32_t)h10 | ((uint32_t)h11 << 16));
                sts_u32(sb + O_XLO + o0, pack_bf2(y00 - bf2f(h00), y01 - bf2f(h01)));
                sts_u32(sb + O_XLO + o1, pack_bf2(y10 - bf2f(h10), y11 - bf2f(h11)));
            }
            CP_WAIT0();                   // W2 image resident
            __syncthreads();
        }
    }

    // ---------- output ----------
    if (cc0 < C_) {
#pragma unroll
        for (int mt = 0; mt < 4; mt++) {
            int p0 = mt * 16 + g, p1 = p0 + 8;
            float* o0 = out + ((size_t)p0 * B_ + b) * C_ + cc0;
            float* o1 = out + ((size_t)p1 * B_ + b) * C_ + cc0;
            *(float2*)o0 = make_float2(acc[mt][0], acc[mt][1]);
            *(float2*)o1 = make_float2(acc[mt][2], acc[mt][3]);
        }
    }
}

// =======================================================================
extern "C" void kernel_launch(void* const* d_in, const int* in_sizes, int n_in,
                              void* d_out, int out_size)
{
    const int*   ids  = (const int*)d_in[0];
    const float* feat = (const float*)d_in[1];
    const float* W1 = (const float*)d_in[2];
    const float* b1 = (const float*)d_in[3];
    const float* Wm = (const float*)d_in[4];
    const float* bm = (const float*)d_in[5];
    const float* W2 = (const float*)d_in[6];
    const float* b2 = (const float*)d_in[7];
    float* out = (float*)d_out;

    cudaFuncSetAttribute(grapher_k1, cudaFuncAttributeMaxDynamicSharedMemorySize, SM1_BYTES);
    cudaFuncSetAttribute(grapher_k2, cudaFuncAttributeMaxDynamicSharedMemorySize, SM2_BYTES);

    grapher_cvt<<<304, 160>>>(Wm, W2);
    grapher_k1<<<B_, NT1, SM1_BYTES>>>(ids, feat, W1, b1);
    grapher_k2<<<B_, NT2, SM2_BYTES>>>(bm, b2, out);
}

// round 15
// speedup vs baseline: 1.7780x; 1.0526x over previous
#include <cuda_runtime.h>
#include <cuda_bf16.h>
#include <cstdint>

// Grapher round 15, two launches (cvt folded into K1):
//  K1 (128 x 1024): scan + means + GEMM1 (mean@W1, fp32) + pair build -> X
//     bf16 hi/lo global image. Spare threads: blocks 0-37 convert Wm/W2 ->
//     bf16 hi/lo transposed global image (19 fully-unrolled LDGs/thread,
//     hidden under the means phase); blocks 38-127 L2-prefetch W1.
//  K2 (128 x 608): cp.async Wm+X (group A) and W2 (group B, drains under
//     layer 1), tensor-core 2-layer MLP (m16n8k16 + k8 tail, 3-term split).

#define B_   128
#define S_   1024
#define H_   768
#define C_   150
#define NN   8
#define SEPID 3

typedef unsigned long long u64;

#define W_IMG_HALF 23104          // 152*152 ushorts per region

// global weight image: WMHI, WMLO, W2HI, W2LO (matches K2 smem block)
__device__ __align__(16) unsigned short g_Wcvt[4 * W_IMG_HALF];
// global X image per batch: Xhi[64][152] then Xlo[64][152] bf16 (9728 u32 / batch)
__device__ __align__(16) uint32_t g_Ximg[B_ * 9728];

// ---------------- helpers ----------------
__device__ __forceinline__ uint32_t sptr(const void* p) {
    return (uint32_t)__cvta_generic_to_shared(p);
}
__device__ __forceinline__ void cp16(uint32_t s, const void* g) {
    asm volatile("cp.async.ca.shared.global [%0], [%1], 16;" :: "r"(s), "l"(g));
}
#define CP_COMMIT() asm volatile("cp.async.commit_group;" ::: "memory")
#define CP_WAIT1()  asm volatile("cp.async.wait_group 1;" ::: "memory")
#define CP_WAIT0()  asm volatile("cp.async.wait_group 0;" ::: "memory")

__device__ __forceinline__ void ffma2(u64& d, u64 a, u64 b) {
    asm("fma.rn.f32x2 %0, %1, %2, %0;" : "+l"(d) : "l"(a), "l"(b));
}
__device__ __forceinline__ u64 add2(u64 a, u64 b) {
    u64 r; asm("add.rn.f32x2 %0, %1, %2;" : "=l"(r) : "l"(a), "l"(b)); return r;
}
__device__ __forceinline__ u64 dup2(float x) {
    u64 r; asm("mov.b64 %0, {%1, %1};" : "=l"(r) : "f"(x)); return r;
}
__device__ __forceinline__ void unpack2(u64 v, float& lo, float& hi) {
    asm("mov.b64 {%0, %1}, %2;" : "=f"(lo), "=f"(hi) : "l"(v));
}
__device__ __forceinline__ u64 lds64(uint32_t a) {
    u64 v; asm volatile("ld.shared.u64 %0, [%1];" : "=l"(v) : "r"(a)); return v;
}
__device__ __forceinline__ void lds_v2(uint32_t a, u64& x, u64& y) {
    asm volatile("ld.shared.v2.u64 {%0, %1}, [%2];" : "=l"(x), "=l"(y) : "r"(a));
}
__device__ __forceinline__ void sts64(uint32_t a, u64 v) {
    asm volatile("st.shared.u64 [%0], %1;" :: "r"(a), "l"(v) : "memory");
}
__device__ __forceinline__ uint32_t lds_u32(uint32_t a) {
    uint32_t v; asm volatile("ld.shared.b32 %0, [%1];" : "=r"(v) : "r"(a)); return v;
}
__device__ __forceinline__ void sts_u32(uint32_t a, uint32_t v) {
    asm volatile("st.shared.b32 [%0], %1;" :: "r"(a), "r"(v) : "memory");
}
__device__ __forceinline__ unsigned short f2bf(float x) {
    __nv_bfloat16 h = __float2bfloat16_rn(x);
    return *reinterpret_cast<unsigned short*>(&h);
}
__device__ __forceinline__ float bf2f(unsigned short u) {
    __nv_bfloat16 h = *reinterpret_cast<__nv_bfloat16*>(&u);
    return __bfloat162float(h);
}
__device__ __forceinline__ uint32_t pack_bf2(float a, float b) {
    return (uint32_t)f2bf(a) | ((uint32_t)f2bf(b) << 16);
}

__device__ __forceinline__ void mma8(float c[4], uint32_t a0, uint32_t a1, uint32_t b0) {
    asm volatile(
        "mma.sync.aligned.m16n8k8.row.col.f32.bf16.bf16.f32 "
        "{%0,%1,%2,%3}, {%4,%5}, {%6}, {%0,%1,%2,%3};"
        : "+f"(c[0]), "+f"(c[1]), "+f"(c[2]), "+f"(c[3])
        : "r"(a0), "r"(a1), "r"(b0));
}
__device__ __forceinline__ void mma16(float c[4], uint32_t a0, uint32_t a1,
                                      uint32_t a2, uint32_t a3,
                                      uint32_t b0, uint32_t b1) {
    asm volatile(
        "mma.sync.aligned.m16n8k16.row.col.f32.bf16.bf16.f32 "
        "{%0,%1,%2,%3}, {%4,%5,%6,%7}, {%8,%9}, {%0,%1,%2,%3};"
        : "+f"(c[0]), "+f"(c[1]), "+f"(c[2]), "+f"(c[3])
        : "r"(a0), "r"(a1), "r"(a2), "r"(a3), "r"(b0), "r"(b1));
}

// =======================================================================
// K1 : scan + means (+ weight cvt / W1 prefetch) + GEMM1 + pair build
// =======================================================================
#define NT1 1024
#define OFF_P   0                 // means partials P[5][8][772]=30880; then GEMM1 partials
#define OFF_MT  30880             // meansT[768][8] = 6144
#define OFF_G   37024             // 8*152
#define OFF_B1  38240             // 152
#define OFF_BND 38392             // 16 ints
#define SM1_FLOATS 38408
#define SM1_BYTES (SM1_FLOATS * 4)   // 153632

__global__ __launch_bounds__(NT1, 1)
void grapher_k1(const int* __restrict__ ids,
                const float* __restrict__ feat,
                const float* __restrict__ W1, const float* __restrict__ b1,
                const float* __restrict__ Wm, const float* __restrict__ W2)
{
    extern __shared__ float sm[];
    float* sP  = sm + OFF_P;
    float* sMT = sm + OFF_MT;
    float* sG  = sm + OFF_G;
    float* sB1 = sm + OFF_B1;
    int*   sBnd = (int*)(sm + OFF_BND);

    const int tid = threadIdx.x;
    const int b   = blockIdx.x;
    const uint32_t mt_b = sptr(sMT);
    const uint32_t pp_b = sptr(sP);

    // ---- scan (warp 0) + b1 load ----
    if (tid < 32) {
        const int lane = tid;
        if (lane < 16) sBnd[lane] = S_;
        __syncwarp();
        const int4* rp = (const int4*)(ids + (size_t)b * S_) + lane * 8;
        int4 v[8];
        int cnt = 0;
#pragma unroll
        for (int q = 0; q < 8; q++) {
            v[q] = rp[q];
            cnt += (v[q].x == SEPID) + (v[q].y == SEPID) +
                   (v[q].z == SEPID) + (v[q].w == SEPID);
        }
        int pre = cnt;
#pragma unroll
        for (int off = 1; off < 32; off <<= 1) {
            int t = __shfl_up_sync(0xffffffffu, pre, off);
            if (lane >= off) pre += t;
        }
        int run = pre - cnt;
#pragma unroll
        for (int q = 0; q < 8; q++) {
            int base = lane * 32 + q * 4;
            if (v[q].x == SEPID) { run++; if (run <= NN) sBnd[run] = base + 0; }
            if (v[q].y == SEPID) { run++; if (run <= NN) sBnd[run] = base + 1; }
            if (v[q].z == SEPID) { run++; if (run <= NN) sBnd[run] = base + 2; }
            if (v[q].w == SEPID) { run++; if (run <= NN) sBnd[run] = base + 3; }
        }
    } else if (tid >= 64 && tid < 64 + 152) {
        int i = tid - 64;
        sB1[i] = (i < C_) ? b1[i] : 0.f;
    }
    __syncthreads();

    // ---- means partials (tid<960) || weight cvt / W1 prefetch (spares) ----
    if (tid < 960) {
        const int tg  = tid / 192;
        const int col = tid - tg * 192;
        const int T   = sBnd[NN];
        const int tb0 = (T * tg) / 5;
        const int tb1 = (T * (tg + 1)) / 5;
        const float4* f4 = (const float4*)(feat + (size_t)b * S_ * H_) + col;
        float* P = sP + tg * 6176 + col * 4;
#pragma unroll 1
        for (int n = 0; n < NN; n++) {
            int lo = (n == 0) ? 0 : sBnd[n] + 1;
            int hi = sBnd[n + 1];
            if (lo < tb0) lo = tb0;
            if (hi > tb1) hi = tb1;
            float4 a0 = make_float4(0.f, 0.f, 0.f, 0.f), a1 = a0, a2 = a0, a3 = a0;
            int t = lo;
            for (; t + 3 < hi; t += 4) {
                float4 v0 = f4[(t + 0) * 192];
                float4 v1 = f4[(t + 1) * 192];
                float4 v2 = f4[(t + 2) * 192];
                float4 v3 = f4[(t + 3) * 192];
                a0.x += v0.x; a0.y += v0.y; a0.z += v0.z; a0.w += v0.w;
                a1.x += v1.x; a1.y += v1.y; a1.z += v1.z; a1.w += v1.w;
                a2.x += v2.x; a2.y += v2.y; a2.z += v2.z; a2.w += v2.w;
                a3.x += v3.x; a3.y += v3.y; a3.z += v3.z; a3.w += v3.w;
            }
            for (; t < hi; t++) {
                float4 v = f4[t * 192];
                a0.x += v.x; a0.y += v.y; a0.z += v.z; a0.w += v.w;
            }
            float4 s;
            s.x = (a0.x + a1.x) + (a2.x + a3.x);
            s.y = (a0.y + a1.y) + (a2.y + a3.y);
            s.z = (a0.z + a1.z) + (a2.z + a3.z);
            s.w = (a0.w + a1.w) + (a2.w + a3.w);
            *(float4*)(P + n * 772) = s;
        }
    } else if (b < 38) {
        // blocks 0-37: convert Wm/W2 -> g_Wcvt (2432 threads x 19 elements,
        // fully unrolled -> 19 independent LDGs, one latency wave)
        const int start = b * 64 + (tid - 960);          // 0..2431
#pragma unroll
        for (int q = 0; q < 19; q++) {
            int idx = start + q * 2432;                  // < 46208
            int layer = idx / (152 * 152);
            int rem = idx - layer * 152 * 152;
            int n = rem / 152, k = rem - n * 152;
            const float* src = layer ? W2 : Wm;
            float v = (k < C_ && n < C_) ? __ldg(src + k * C_ + n) : 0.f;
            unsigned short h = f2bf(v);
            unsigned short l = f2bf(v - bf2f(h));
            int base = layer * 2 * W_IMG_HALF;
            g_Wcvt[base + rem] = h;
            g_Wcvt[base + W_IMG_HALF + rem] = l;
        }
    } else {
        // blocks 38-127: L2-prefetch W1 for GEMM1 (L2 is chip-shared)
        const float4* w4 = (const float4*)W1;
        for (int i = tid - 960; i < (H_ * C_) / 4; i += 64)
            asm volatile("prefetch.global.L2 [%0];" :: "l"(w4 + i));
    }
    __syncthreads();

    // ---- combine tiles + 1/len -> meansT[k][8] ----
    if (tid < H_) {
        float inv[8];
#pragma unroll
        for (int n = 0; n < NN; n++) {
            int lo = (n == 0) ? 0 : sBnd[n] + 1;
            int len = sBnd[n + 1] - lo;
            if (len < 1) len = 1;
            inv[n] = 1.0f / (float)len;
        }
        const float* P = sP + tid;
#pragma unroll
        for (int n = 0; n < NN; n++) {
            float s = ((P[n * 772] + P[6176 + n * 772]) +
                       (P[12352 + n * 772] + P[18528 + n * 772])) + P[24704 + n * 772];
            sMT[tid * 8 + n] = s * inv[n];
        }
    }
    __syncthreads();                      // P region free for GEMM1 partials

    // ---- GEMM1 (fp32 FFMA2): g[n][c] = sum_k meansT[k][n] * W1[k][c] ----
    u64 g_acc[2][4];
    int ks1 = 0, cpair = 0;
    if (tid < 600) {
        ks1 = tid / 75; cpair = tid - ks1 * 75;
#pragma unroll
        for (int cc = 0; cc < 2; cc++)
#pragma unroll
            for (int q = 0; q < 4; q++) g_acc[cc][q] = 0ull;
        const float2* wrow = (const float2*)(W1 + (size_t)(ks1 * 96) * C_) + cpair;
#pragma unroll 4
        for (int kk = 0; kk < 96; kk++) {
            int k = ks1 * 96 + kk;
            float2 w = __ldg(wrow + kk * 75);
            u64 dw0 = dup2(w.x), dw1 = dup2(w.y);
            u64 m01, m23, m45, m67;
            uint32_t ma = mt_b + (uint32_t)(k * 8) * 4u;
            lds_v2(ma, m01, m23);
            lds_v2(ma + 16u, m45, m67);
            ffma2(g_acc[0][0], m01, dw0); ffma2(g_acc[0][1], m23, dw0);
            ffma2(g_acc[0][2], m45, dw0); ffma2(g_acc[0][3], m67, dw0);
            ffma2(g_acc[1][0], m01, dw1); ffma2(g_acc[1][1], m23, dw1);
            ffma2(g_acc[1][2], m45, dw1); ffma2(g_acc[1][3], m67, dw1);
        }
    }
    __syncthreads();
    if (tid < 600) {
#pragma unroll
        for (int cc = 0; cc < 2; cc++)
#pragma unroll
            for (int q = 0; q < 4; q++)
                sts64(pp_b + (uint32_t)(ks1 * 1200 + (cc * 4 + q) * 150 + 2 * cpair) * 4u,
                      g_acc[cc][q]);
    }
    __syncthreads();
    if (tid < 600) {
        u64 s = lds64(pp_b + (uint32_t)(2 * tid) * 4u);
#pragma unroll
        for (int k8 = 1; k8 < 8; k8++)
            s = add2(s, lds64(pp_b + (uint32_t)(k8 * 1200 + 2 * tid) * 4u));
        int e = tid / 75, cp2 = tid - e * 75;
        int cc = e >> 2, q = e & 3, c = 2 * cp2 + cc;
        float lo, hi; unpack2(s, lo, hi);
        sG[(2 * q + 0) * 152 + c] = lo;
        sG[(2 * q + 1) * 152 + c] = hi;
    }
    __syncthreads();

    // ---- pair build -> g_Ximg[b]: Xhi then Xlo, bf16, pads zero ----
    {
        const int p  = tid >> 4;          // 0..63
        const int cs = tid & 15;          // 16 col segments of 10
        const int i  = p >> 3, j = p & 7;
        const int c0 = cs * 10;
        uint32_t* dhi = g_Ximg + (size_t)b * 9728 + p * 76;
        uint32_t* dlo = dhi + 4864;
#pragma unroll
        for (int m = 0; m < 5; m++) {
            int c = c0 + 2 * m;
            if (c < 152) {
                float v0 = 0.f, v1 = 0.f;
                if (c < C_)
                    v0 = fmaxf(sG[i * 152 + c] - sG[j * 152 + c] + sB1[c], 0.f);
                if (c + 1 < C_)
                    v1 = fmaxf(sG[i * 152 + c + 1] - sG[j * 152 + c + 1] + sB1[c + 1], 0.f);
                unsigned short h0 = f2bf(v0), h1 = f2bf(v1);
                dhi[c >> 1] = (uint32_t)h0 | ((uint32_t)h1 << 16);
                dlo[c >> 1] = pack_bf2(v0 - bf2f(h0), v1 - bf2f(h1));
            }
        }
    }
}

// =======================================================================
// K2 : tensor-core 2-layer MLP (per batch)
// =======================================================================
#define NT2 608
#define O_WMHI 0
#define O_WMLO 46208
#define O_W2HI 92416
#define O_W2LO 138624
#define O_X    184832     // Xhi bf16 [64][152]
#define O_XLO  204288     // Xlo bf16 [64][152]
#define SM2_BYTES 223744

__global__ __launch_bounds__(NT2, 1)
void grapher_k2(const float* __restrict__ bm, const float* __restrict__ b2,
                float* __restrict__ out)
{
    extern __shared__ char smc[];
    const uint32_t sb = sptr(smc);
    const int tid = threadIdx.x;
    const int b   = blockIdx.x;

    // ---- group A: Wm hi/lo (5776 cp16) + X image (2432 cp16) ----
    {
        const uint4* wsrc = (const uint4*)g_Wcvt;
        const uint4* xsrc = (const uint4*)(g_Ximg + (size_t)b * 9728);
        for (int i = tid; i < 8208; i += NT2) {
            if (i < 5776) cp16(sb + O_WMHI + (uint32_t)i * 16u, wsrc + i);
            else          cp16(sb + O_X + (uint32_t)(i - 5776) * 16u, xsrc + (i - 5776));
        }
        CP_COMMIT();
        // ---- group B: W2 hi/lo (drains under layer 1) ----
        for (int i = tid; i < 5776; i += NT2)
            cp16(sb + O_W2HI + (uint32_t)i * 16u, wsrc + 5776 + i);
        CP_COMMIT();
    }

    const int lane = tid & 31;
    const int g    = lane >> 2;           // 0..7
    const int tg   = lane & 3;            // 0..3
    const int n0   = (tid >> 5) * 8;      // warp's n8 tile
    const int cc0  = n0 + 2 * tg;

    CP_WAIT1();                           // group A resident (Wm + X)
    __syncthreads();

    float acc[4][4];

#pragma unroll 1
    for (int L = 0; L < 2; L++) {
        const uint32_t whb = sb + (L ? O_W2HI : O_WMHI);
        const uint32_t wlb = sb + (L ? O_W2LO : O_WMLO);
        const float* bias = L ? b2 : bm;
        {
            float bv0 = (cc0 < C_)     ? __ldg(bias + cc0)     : 0.f;
            float bv1 = (cc0 + 1 < C_) ? __ldg(bias + cc0 + 1) : 0.f;
#pragma unroll
            for (int mt = 0; mt < 4; mt++) {
                acc[mt][0] = bv0; acc[mt][1] = bv1;
                acc[mt][2] = bv0; acc[mt][3] = bv1;
            }
        }
        const uint32_t brow = whb + (uint32_t)((n0 + g) * 304);
        const uint32_t brol = wlb + (uint32_t)((n0 + g) * 304);

#pragma unroll 1
        for (int ks = 0; ks < 9; ks++) {              // k = 16*ks .. +15
            const uint32_t kb = (uint32_t)(ks * 32 + tg * 4);
            uint32_t bh0 = lds_u32(brow + kb);
            uint32_t bh1 = lds_u32(brow + kb + 16u);
            uint32_t bl0 = lds_u32(brol + kb);
            uint32_t bl1 = lds_u32(brol + kb + 16u);
#pragma unroll
            for (int mt = 0; mt < 4; mt++) {
                uint32_t r0off = (uint32_t)((mt * 16 + g) * 304) + kb;
                uint32_t r1off = r0off + 8u * 304u;
                uint32_t ah0 = lds_u32(sb + O_X + r0off);
                uint32_t ah1 = lds_u32(sb + O_X + r1off);
                uint32_t ah2 = lds_u32(sb + O_X + r0off + 16u);
                uint32_t ah3 = lds_u32(sb + O_X + r1off + 16u);
                uint32_t al0 = lds_u32(sb + O_XLO + r0off);
                uint32_t al1 = lds_u32(sb + O_XLO + r1off);
                uint32_t al2 = lds_u32(sb + O_XLO + r0off + 16u);
                uint32_t al3 = lds_u32(sb + O_XLO + r1off + 16u);
                mma16(acc[mt], ah0, ah1, ah2, ah3, bh0, bh1);
                mma16(acc[mt], ah0, ah1, ah2, ah3, bl0, bl1);
                mma16(acc[mt], al0, al1, al2, al3, bh0, bh1);
            }
        }
        {                                              // k8 tail: k = 144..151
            const uint32_t kb = (uint32_t)(288 + tg * 4);
            uint32_t bh = lds_u32(brow + kb);
            uint32_t bl = lds_u32(brol + kb);
#pragma unroll
            for (int mt = 0; mt < 4; mt++) {
                uint32_t r0off = (uint32_t)((mt * 16 + g) * 304) + kb;
                uint32_t r1off = r0off + 8u * 304u;
                uint32_t ah0 = lds_u32(sb + O_X + r0off);
                uint32_t ah1 = lds_u32(sb + O_X + r1off);
                uint32_t al0 = lds_u32(sb + O_XLO + r0off);
                uint32_t al1 = lds_u32(sb + O_XLO + r1off);
                mma8(acc[mt], ah0, ah1, bh);
                mma8(acc[mt], ah0, ah1, bl);
                mma8(acc[mt], al0, al1, bh);
            }
        }
        __syncthreads();                  // all X reads for this layer done

        if (L == 0) {
            // y = relu(acc) -> re-split into Xhi/Xlo (layer-2 input)
#pragma unroll
            for (int mt = 0; mt < 4; mt++) {
                int r0 = mt * 16 + g, r1 = r0 + 8;
                float y00 = fmaxf(acc[mt][0], 0.f), y01 = fmaxf(acc[mt][1], 0.f);
                float y10 = fmaxf(acc[mt][2], 0.f), y11 = fmaxf(acc[mt][3], 0.f);
                unsigned short h00 = f2bf(y00), h01 = f2bf(y01);
                unsigned short h10 = f2bf(y10), h11 = f2bf(y11);
                uint32_t o0 = (uint32_t)(r0 * 152 + cc0) * 2u;
                uint32_t o1 = (uint32_t)(r1 * 152 + cc0) * 2u;
                sts_u32(sb + O_X   + o0, (uint32_t)h00 | ((uint32_t)h01 << 16));
                sts_u32(sb + O_X   + o1, (uint32_t)h10 | ((uint32_t)h11 << 16));
                sts_u32(sb + O_XLO + o0, pack_bf2(y00 - bf2f(h00), y01 - bf2f(h01)));
                sts_u32(sb + O_XLO + o1, pack_bf2(y10 - bf2f(h10), y11 - bf2f(h11)));
            }
            CP_WAIT0();                   // W2 image resident
            __syncthreads();
        }
    }

    // ---------- output ----------
    if (cc0 < C_) {
#pragma unroll
        for (int mt = 0; mt < 4; mt++) {
            int p0 = mt * 16 + g, p1 = p0 + 8;
            float* o0 = out + ((size_t)p0 * B_ + b) * C_ + cc0;
            float* o1 = out + ((size_t)p1 * B_ + b) * C_ + cc0;
            *(float2*)o0 = make_float2(acc[mt][0], acc[mt][1]);
            *(float2*)o1 = make_float2(acc[mt][2], acc[mt][3]);
        }
    }
}

// =======================================================================
extern "C" void kernel_launch(void* const* d_in, const int* in_sizes, int n_in,
                              void* d_out, int out_size)
{
    const int*   ids  = (const int*)d_in[0];
    const float* feat = (const float*)d_in[1];
    const float* W1 = (const float*)d_in[2];
    const float* b1 = (const float*)d_in[3];
    const float* Wm = (const float*)d_in[4];
    const float* bm = (const float*)d_in[5];
    const float* W2 = (const float*)d_in[6];
    const float* b2 = (const float*)d_in[7];
    float* out = (float*)d_out;

    cudaFuncSetAttribute(grapher_k1, cudaFuncAttributeMaxDynamicSharedMemorySize, SM1_BYTES);
    cudaFuncSetAttribute(grapher_k2, cudaFuncAttributeMaxDynamicSharedMemorySize, SM2_BYTES);

    grapher_k1<<<B_, NT1, SM1_BYTES>>>(ids, feat, W1, b1, Wm, W2);
    grapher_k2<<<B_, NT2, SM2_BYTES>>>(bm, b2, out);
}